// round 1
// baseline (speedup 1.0000x reference)
#include <cuda_runtime.h>

#define B 4
#define T 2048
#define H 1024
#define NH 16
#define DH 64
#define BH (B*NH)
#define QTILES (T/64)

// Scratch (static device allocations — allowed; no runtime allocs anywhere)
__device__ float Qg[BH * T * DH];          // [b,h,t,d]
__device__ float Kg[BH * T * DH];
__device__ float Vg[BH * T * DH];
__device__ float Psum[BH * QTILES * DH];   // per (bh, qtile) column sums of O
__device__ float Mctx[B * H];              // mean over T of ctx, [b, h*DH+d]

// ---------------------------------------------------------------------------
// Kernel 1: fused QKV projection. y = x @ W^T, written head-split.
// grid = (M/64=128, 48) : gridDim.y selects {Wq,Wk,Wv} x head
// ---------------------------------------------------------------------------
__global__ __launch_bounds__(256) void proj_kernel(
    const float* __restrict__ x, const float* __restrict__ Wq,
    const float* __restrict__ Wk, const float* __restrict__ Wv)
{
    __shared__ float As[64][17];
    __shared__ float Bs[64][17];

    const int bm = blockIdx.x;              // row tile
    const int bn = blockIdx.y;              // 0..47
    const int which = bn >> 4;              // 0=Q 1=K 2=V
    const int h = bn & 15;                  // head (64-col tile == one head)
    const int ncol0 = h * 64;

    const float* __restrict__ W = (which == 0) ? Wq : (which == 1) ? Wk : Wv;
    float* __restrict__ Og = (which == 0) ? Qg : (which == 1) ? Kg : Vg;

    const int tid = threadIdx.x;
    const int tx = tid & 15, ty = tid >> 4;
    const int m0 = bm * 64;

    float acc[4][4];
    #pragma unroll
    for (int i = 0; i < 4; i++)
        #pragma unroll
        for (int j = 0; j < 4; j++) acc[i][j] = 0.f;

    const int lr = tid >> 2;                // load row 0..63
    const int lc = (tid & 3) * 4;           // load col chunk

    for (int k0 = 0; k0 < H; k0 += 16) {
        float4 av = *(const float4*)(x + (size_t)(m0 + lr) * H + k0 + lc);
        float4 bv = *(const float4*)(W + (size_t)(ncol0 + lr) * H + k0 + lc);
        As[lr][lc+0] = av.x; As[lr][lc+1] = av.y; As[lr][lc+2] = av.z; As[lr][lc+3] = av.w;
        Bs[lr][lc+0] = bv.x; Bs[lr][lc+1] = bv.y; Bs[lr][lc+2] = bv.z; Bs[lr][lc+3] = bv.w;
        __syncthreads();
        #pragma unroll
        for (int kk = 0; kk < 16; kk++) {
            float a0 = As[ty*4+0][kk], a1 = As[ty*4+1][kk];
            float a2 = As[ty*4+2][kk], a3 = As[ty*4+3][kk];
            float b0 = Bs[tx*4+0][kk], b1 = Bs[tx*4+1][kk];
            float b2 = Bs[tx*4+2][kk], b3 = Bs[tx*4+3][kk];
            acc[0][0] += a0*b0; acc[0][1] += a0*b1; acc[0][2] += a0*b2; acc[0][3] += a0*b3;
            acc[1][0] += a1*b0; acc[1][1] += a1*b1; acc[1][2] += a1*b2; acc[1][3] += a1*b3;
            acc[2][0] += a2*b0; acc[2][1] += a2*b1; acc[2][2] += a2*b2; acc[2][3] += a2*b3;
            acc[3][0] += a3*b0; acc[3][1] += a3*b1; acc[3][2] += a3*b2; acc[3][3] += a3*b3;
        }
        __syncthreads();
    }

    // m0..m0+63 lies within one batch (T % 64 == 0)
    const int b  = m0 / T;
    const int t0 = m0 - b * T;
    float* __restrict__ dst = Og + (size_t)(b * NH + h) * T * DH;
    #pragma unroll
    for (int i = 0; i < 4; i++)
        #pragma unroll
        for (int j = 0; j < 4; j++)
            dst[(size_t)(t0 + ty*4 + i) * DH + (tx*4 + j)] = acc[i][j];
}

// ---------------------------------------------------------------------------
// Kernel 2: flash attention per (b,h), 64-query tiles, 32-key tiles.
// Emits per-block column sums (deterministic, no atomics).
// grid = (QTILES=32, BH=64), 256 threads
// ---------------------------------------------------------------------------
__global__ __launch_bounds__(256) void attn_kernel()
{
    __shared__ float Qs[64][65];
    __shared__ float Ks[32][65];
    __shared__ float Vs[32][65];
    __shared__ float Ps[64][33];

    const int qt = blockIdx.x;
    const int bh = blockIdx.y;
    const float* __restrict__ Qp = Qg + (size_t)bh * T * DH;
    const float* __restrict__ Kp = Kg + (size_t)bh * T * DH;
    const float* __restrict__ Vp = Vg + (size_t)bh * T * DH;

    const int tid = threadIdx.x;
    const int tx = tid & 15, ty = tid >> 4;
    const int q0 = qt * 64;

    // Load Q tile (64 x 64)
    for (int i = tid; i < 64 * 16; i += 256) {
        int r = i >> 4, c = (i & 15) * 4;
        float4 v = *(const float4*)(Qp + (size_t)(q0 + r) * DH + c);
        Qs[r][c] = v.x; Qs[r][c+1] = v.y; Qs[r][c+2] = v.z; Qs[r][c+3] = v.w;
    }

    float mi[4], li[4], acc[4][4];
    #pragma unroll
    for (int i = 0; i < 4; i++) {
        mi[i] = -1e30f; li[i] = 0.f;
        #pragma unroll
        for (int j = 0; j < 4; j++) acc[i][j] = 0.f;
    }
    __syncthreads();

    for (int s0 = 0; s0 < T; s0 += 32) {
        // Load K,V tiles (32 x 64 each)
        for (int i = tid; i < 512; i += 256) {
            int r = i >> 4, c = (i & 15) * 4;
            float4 kv = *(const float4*)(Kp + (size_t)(s0 + r) * DH + c);
            Ks[r][c] = kv.x; Ks[r][c+1] = kv.y; Ks[r][c+2] = kv.z; Ks[r][c+3] = kv.w;
            float4 vv = *(const float4*)(Vp + (size_t)(s0 + r) * DH + c);
            Vs[r][c] = vv.x; Vs[r][c+1] = vv.y; Vs[r][c+2] = vv.z; Vs[r][c+3] = vv.w;
        }
        __syncthreads();

        // S = Q K^T : thread -> 4 rows x 2 cols
        float sv0[4], sv1[4];
        #pragma unroll
        for (int i = 0; i < 4; i++) { sv0[i] = 0.f; sv1[i] = 0.f; }
        #pragma unroll
        for (int k = 0; k < 64; k++) {
            float b0 = Ks[tx*2+0][k], b1 = Ks[tx*2+1][k];
            #pragma unroll
            for (int i = 0; i < 4; i++) {
                float a = Qs[ty*4+i][k];
                sv0[i] += a * b0; sv1[i] += a * b1;
            }
        }

        // Online softmax (row groups of 16 lanes, warp-aligned)
        #pragma unroll
        for (int i = 0; i < 4; i++) {
            float x0 = sv0[i] * 0.125f;
            float x1 = sv1[i] * 0.125f;
            float mloc = fmaxf(x0, x1);
            #pragma unroll
            for (int d = 1; d < 16; d <<= 1)
                mloc = fmaxf(mloc, __shfl_xor_sync(0xffffffffu, mloc, d));
            float mn = fmaxf(mi[i], mloc);
            float p0 = __expf(x0 - mn);
            float p1 = __expf(x1 - mn);
            float alpha = __expf(mi[i] - mn);
            float rs = p0 + p1;
            #pragma unroll
            for (int d = 1; d < 16; d <<= 1)
                rs += __shfl_xor_sync(0xffffffffu, rs, d);
            li[i] = li[i] * alpha + rs;
            mi[i] = mn;
            #pragma unroll
            for (int j = 0; j < 4; j++) acc[i][j] *= alpha;
            Ps[ty*4+i][tx*2+0] = p0;
            Ps[ty*4+i][tx*2+1] = p1;
        }
        __syncthreads();

        // O += P V : thread -> 4 rows x 4 cols
        #pragma unroll
        for (int k = 0; k < 32; k++) {
            float v0 = Vs[k][tx*4+0], v1 = Vs[k][tx*4+1];
            float v2 = Vs[k][tx*4+2], v3 = Vs[k][tx*4+3];
            #pragma unroll
            for (int i = 0; i < 4; i++) {
                float p = Ps[ty*4+i][k];
                acc[i][0] += p*v0; acc[i][1] += p*v1;
                acc[i][2] += p*v2; acc[i][3] += p*v3;
            }
        }
        __syncthreads();
    }

    // Column partials: sum over this thread's 4 rows of O = acc/li
    float rinv[4];
    #pragma unroll
    for (int i = 0; i < 4; i++) rinv[i] = 1.f / li[i];
    float part[4];
    #pragma unroll
    for (int j = 0; j < 4; j++) {
        part[j] = acc[0][j]*rinv[0] + acc[1][j]*rinv[1]
                + acc[2][j]*rinv[2] + acc[3][j]*rinv[3];
    }

    // Block reduce over ty (16 groups) via shared scratch (reuse Qs)
    float* red = &Qs[0][0];   // need 16*64 floats
    #pragma unroll
    for (int j = 0; j < 4; j++) red[ty*64 + tx*4 + j] = part[j];
    __syncthreads();
    if (tid < 64) {
        float s = 0.f;
        #pragma unroll
        for (int r = 0; r < 16; r++) s += red[r*64 + tid];
        Psum[((size_t)bh * QTILES + qt) * DH + tid] = s;
    }
}

// ---------------------------------------------------------------------------
// Kernel 3: deterministic reduce of q-tile partials -> mean context
// ---------------------------------------------------------------------------
__global__ __launch_bounds__(256) void reduce_kernel()
{
    int idx = blockIdx.x * 256 + threadIdx.x;   // 0..4095
    int b = idx >> 10;
    int h = (idx >> 6) & 15;
    int d = idx & 63;
    int bh = b * NH + h;
    float s = 0.f;
    #pragma unroll
    for (int qt = 0; qt < QTILES; qt++)
        s += Psum[((size_t)bh * QTILES + qt) * DH + d];
    Mctx[idx] = s * (1.0f / T);
}

// ---------------------------------------------------------------------------
// Kernel 4: out[b,n] = Mctx[b,:] . Wo[n,:] + bo[n]   (warp per output)
// grid = 512 x 256 threads = 4096 warps
// ---------------------------------------------------------------------------
__global__ __launch_bounds__(256) void out_kernel(
    const float* __restrict__ Wo, const float* __restrict__ bo,
    float* __restrict__ out)
{
    int gw = (blockIdx.x * 256 + threadIdx.x) >> 5;   // 0..4095
    int lane = threadIdx.x & 31;
    int b = gw >> 10;
    int n = gw & 1023;
    const float* __restrict__ wrow = Wo + (size_t)n * H;
    const float* __restrict__ mrow = Mctx + b * H;
    float s = 0.f;
    #pragma unroll 4
    for (int k = lane; k < H; k += 32) s += mrow[k] * wrow[k];
    #pragma unroll
    for (int d = 16; d; d >>= 1) s += __shfl_xor_sync(0xffffffffu, s, d);
    if (lane == 0) out[b * H + n] = s + bo[n];
}

// ---------------------------------------------------------------------------
extern "C" void kernel_launch(void* const* d_in, const int* in_sizes, int n_in,
                              void* d_out, int out_size)
{
    const float* x  = (const float*)d_in[0];
    const float* Wq = (const float*)d_in[1];
    const float* Wk = (const float*)d_in[2];
    const float* Wv = (const float*)d_in[3];
    const float* Wo = (const float*)d_in[4];
    const float* bo = (const float*)d_in[5];
    float* out = (float*)d_out;

    proj_kernel<<<dim3(128, 48), 256>>>(x, Wq, Wk, Wv);
    attn_kernel<<<dim3(QTILES, BH), 256>>>();
    reduce_kernel<<<16, 256>>>();
    out_kernel<<<512, 256>>>(Wo, bo, out);
}

// round 2
// speedup vs baseline: 1.2692x; 1.2692x over previous
#include <cuda_runtime.h>

#define B 4
#define T 2048
#define H 1024
#define NH 16
#define DH 64
#define BH (B*NH)
#define QTILES (T/64)

typedef unsigned long long u64;

__device__ __forceinline__ u64 pk2(float lo, float hi) {
    u64 r; asm("mov.b64 %0,{%1,%2};" : "=l"(r) : "f"(lo), "f"(hi)); return r;
}
__device__ __forceinline__ void up2(u64 v, float& lo, float& hi) {
    asm("mov.b64 {%0,%1},%2;" : "=f"(lo), "=f"(hi) : "l"(v));
}
__device__ __forceinline__ u64 ffma2(u64 a, u64 b, u64 c) {
    u64 d; asm("fma.rn.f32x2 %0,%1,%2,%3;" : "=l"(d) : "l"(a), "l"(b), "l"(c)); return d;
}
__device__ __forceinline__ u64 fmul2(u64 a, u64 b) {
    u64 d; asm("mul.rn.f32x2 %0,%1,%2;" : "=l"(d) : "l"(a), "l"(b)); return d;
}

// Scratch
__device__ float Qg[BH * T * DH];
__device__ float Kg[BH * T * DH];
__device__ float Vg[BH * T * DH];
__device__ float Psum[BH * QTILES * DH];
__device__ float Mctx[B * H];

// ---------------------------------------------------------------------------
// Kernel 1: projection GEMM, y = x @ W^T, head-split output.
// Block tile 128x128, thread tile 8x8 (split 4+4), FFMA2, k-major smem.
// grid = (64, 8, 3)
// ---------------------------------------------------------------------------
#define PSTRIDE 132

__global__ __launch_bounds__(256) void proj_kernel(
    const float* __restrict__ x, const float* __restrict__ Wq,
    const float* __restrict__ Wk, const float* __restrict__ Wv)
{
    __shared__ float Ast[16 * PSTRIDE];
    __shared__ float Bst[16 * PSTRIDE];

    const int which = blockIdx.z;
    const float* __restrict__ W = (which == 0) ? Wq : (which == 1) ? Wk : Wv;
    float* __restrict__ Og = (which == 0) ? Qg : (which == 1) ? Kg : Vg;

    const int m0 = blockIdx.x * 128;
    const int n0 = blockIdx.y * 128;
    const int tid = threadIdx.x;
    const int tx = tid & 15, ty = tid >> 4;

    u64 acc[8][4];
    #pragma unroll
    for (int i = 0; i < 8; i++)
        #pragma unroll
        for (int j = 0; j < 4; j++) acc[i][j] = 0ull;

    for (int k0 = 0; k0 < H; k0 += 16) {
        // Load & transpose A,B tiles (128 rows x 16 k each)
        #pragma unroll
        for (int j = 0; j < 2; j++) {
            int idx = tid + 256 * j;
            int r = idx >> 2;              // 0..127
            int kc = (idx & 3) * 4;        // 0,4,8,12
            float4 av = *(const float4*)(x + (size_t)(m0 + r) * H + k0 + kc);
            Ast[(kc+0)*PSTRIDE + r] = av.x; Ast[(kc+1)*PSTRIDE + r] = av.y;
            Ast[(kc+2)*PSTRIDE + r] = av.z; Ast[(kc+3)*PSTRIDE + r] = av.w;
            float4 bv = *(const float4*)(W + (size_t)(n0 + r) * H + k0 + kc);
            Bst[(kc+0)*PSTRIDE + r] = bv.x; Bst[(kc+1)*PSTRIDE + r] = bv.y;
            Bst[(kc+2)*PSTRIDE + r] = bv.z; Bst[(kc+3)*PSTRIDE + r] = bv.w;
        }
        __syncthreads();

        #pragma unroll
        for (int kk = 0; kk < 16; kk++) {
            float4 a0 = *(const float4*)&Ast[kk*PSTRIDE + 4*ty];
            float4 a1 = *(const float4*)&Ast[kk*PSTRIDE + 64 + 4*ty];
            float4 b0 = *(const float4*)&Bst[kk*PSTRIDE + 4*tx];
            float4 b1 = *(const float4*)&Bst[kk*PSTRIDE + 64 + 4*tx];
            u64 bp[4] = { pk2(b0.x,b0.y), pk2(b0.z,b0.w),
                          pk2(b1.x,b1.y), pk2(b1.z,b1.w) };
            float av[8] = { a0.x,a0.y,a0.z,a0.w, a1.x,a1.y,a1.z,a1.w };
            #pragma unroll
            for (int i = 0; i < 8; i++) {
                u64 ap = pk2(av[i], av[i]);
                #pragma unroll
                for (int j = 0; j < 4; j++)
                    acc[i][j] = ffma2(ap, bp[j], acc[i][j]);
            }
        }
        __syncthreads();
    }

    // Epilogue: head-split store
    #pragma unroll
    for (int i = 0; i < 8; i++) {
        int rl = (i < 4) ? (4*ty + i) : (64 + 4*ty + i - 4);
        int m = m0 + rl;
        int b = m >> 11;          // /T
        int t = m & 2047;
        #pragma unroll
        for (int jp = 0; jp < 4; jp++) {
            float lo, hi; up2(acc[i][jp], lo, hi);
            int cbase = (jp < 2) ? (4*tx + 2*jp) : (64 + 4*tx + 2*(jp-2));
            int col0 = n0 + cbase;
            int h0 = col0 >> 6, d0 = col0 & 63;
            float* dst = Og + ((size_t)(b*NH + h0) * T + t) * DH + d0;
            dst[0] = lo; dst[1] = hi;   // same head: d0 is even, no boundary cross
        }
    }
}

// ---------------------------------------------------------------------------
// Kernel 2: flash attention, Q-tile 64, K/V-tile 64 (shared buffer), FFMA2.
// grid = (QTILES=32, BH=64), 256 threads. Static smem = 48KB.
// ---------------------------------------------------------------------------
__device__ __forceinline__ int swz(int r, int c) { return (c + (r & ~3)) & 63; }

__global__ __launch_bounds__(256) void attn_kernel()
{
    __shared__ float Qst[64 * 64];   // d-major, swizzled
    __shared__ float Kv[64 * 64];    // K: d-major swizzled; later V: s-major natural
    __shared__ float Pst[64 * 64];   // s-major, swizzled; reused as reduce scratch

    const int qt = blockIdx.x;
    const int bh = blockIdx.y;
    const float* __restrict__ Qp = Qg + (size_t)bh * T * DH;
    const float* __restrict__ Kp = Kg + (size_t)bh * T * DH;
    const float* __restrict__ Vp = Vg + (size_t)bh * T * DH;

    const int tid = threadIdx.x;
    const int tx = tid & 15, ty = tid >> 4;
    const int q0 = qt * 64;

    // Load Q (64x64) transposed + swizzled
    #pragma unroll
    for (int j = 0; j < 4; j++) {
        int idx = tid + 256 * j;
        int r = idx >> 4;              // source row (m)
        int kc = (idx & 15) * 4;       // d chunk
        float4 v = *(const float4*)(Qp + (size_t)(q0 + r) * DH + kc);
        Qst[(kc+0)*64 + swz(kc+0, r)] = v.x;
        Qst[(kc+1)*64 + swz(kc+1, r)] = v.y;
        Qst[(kc+2)*64 + swz(kc+2, r)] = v.z;
        Qst[(kc+3)*64 + swz(kc+3, r)] = v.w;
    }

    float mi[4], li[4];
    u64 accs[4][2], acco[4][2];
    #pragma unroll
    for (int i = 0; i < 4; i++) {
        mi[i] = -1e30f; li[i] = 0.f;
        accs[i][0] = accs[i][1] = 0ull;
        acco[i][0] = acco[i][1] = 0ull;
    }

    for (int s0 = 0; s0 < T; s0 += 64) {
        // Load K transposed + swizzled into Kv
        #pragma unroll
        for (int j = 0; j < 4; j++) {
            int idx = tid + 256 * j;
            int r = idx >> 4;
            int kc = (idx & 15) * 4;
            float4 v = *(const float4*)(Kp + (size_t)(s0 + r) * DH + kc);
            Kv[(kc+0)*64 + swz(kc+0, r)] = v.x;
            Kv[(kc+1)*64 + swz(kc+1, r)] = v.y;
            Kv[(kc+2)*64 + swz(kc+2, r)] = v.z;
            Kv[(kc+3)*64 + swz(kc+3, r)] = v.w;
        }
        __syncthreads();

        // S = Q K^T : thread tile 4m x 4s (2 pairs along s)
        #pragma unroll
        for (int i = 0; i < 4; i++) { accs[i][0] = 0ull; accs[i][1] = 0ull; }
        for (int d0 = 0; d0 < 64; d0 += 4) {
            int qb = (4*ty + d0) & 63;
            int kb = (4*tx + d0) & 63;
            #pragma unroll
            for (int dd = 0; dd < 4; dd++) {
                int d = d0 + dd;
                float4 a = *(const float4*)&Qst[d*64 + qb];
                float4 bv = *(const float4*)&Kv[d*64 + kb];
                u64 bp0 = pk2(bv.x, bv.y), bp1 = pk2(bv.z, bv.w);
                float av[4] = { a.x, a.y, a.z, a.w };
                #pragma unroll
                for (int i = 0; i < 4; i++) {
                    u64 ap = pk2(av[i], av[i]);
                    accs[i][0] = ffma2(ap, bp0, accs[i][0]);
                    accs[i][1] = ffma2(ap, bp1, accs[i][1]);
                }
            }
        }

        // Online softmax per row + store P (transposed, swizzled)
        #pragma unroll
        for (int i = 0; i < 4; i++) {
            float x0, x1, x2, x3;
            up2(accs[i][0], x0, x1);
            up2(accs[i][1], x2, x3);
            x0 *= 0.125f; x1 *= 0.125f; x2 *= 0.125f; x3 *= 0.125f;
            float mloc = fmaxf(fmaxf(x0, x1), fmaxf(x2, x3));
            #pragma unroll
            for (int msk = 1; msk < 16; msk <<= 1)
                mloc = fmaxf(mloc, __shfl_xor_sync(0xffffffffu, mloc, msk));
            float mn = fmaxf(mi[i], mloc);
            float p0 = __expf(x0 - mn), p1 = __expf(x1 - mn);
            float p2 = __expf(x2 - mn), p3 = __expf(x3 - mn);
            float alpha = __expf(mi[i] - mn);
            float rs = (p0 + p1) + (p2 + p3);
            #pragma unroll
            for (int msk = 1; msk < 16; msk <<= 1)
                rs += __shfl_xor_sync(0xffffffffu, rs, msk);
            li[i] = li[i] * alpha + rs;
            mi[i] = mn;
            u64 al2 = pk2(alpha, alpha);
            acco[i][0] = fmul2(acco[i][0], al2);
            acco[i][1] = fmul2(acco[i][1], al2);
            int col = (4*ty + i + 4*tx) & 63;   // swz(s, 4ty+i), s&~3 == 4tx
            Pst[(4*tx+0)*64 + col] = p0;
            Pst[(4*tx+1)*64 + col] = p1;
            Pst[(4*tx+2)*64 + col] = p2;
            Pst[(4*tx+3)*64 + col] = p3;
        }
        __syncthreads();

        // Load V (natural s-major) into Kv
        #pragma unroll
        for (int j = 0; j < 4; j++) {
            int idx = tid + 256 * j;
            int r = idx >> 4;
            int kc = (idx & 15) * 4;
            float4 v = *(const float4*)(Vp + (size_t)(s0 + r) * DH + kc);
            *(float4*)&Kv[r*64 + kc] = v;
        }
        __syncthreads();

        // O += P V : thread tile 4m x 4d (2 pairs along d)
        for (int sb = 0; sb < 64; sb += 4) {
            int pb = (4*ty + sb) & 63;
            #pragma unroll
            for (int ss = 0; ss < 4; ss++) {
                int s = sb + ss;
                float4 a = *(const float4*)&Pst[s*64 + pb];
                float4 bv = *(const float4*)&Kv[s*64 + 4*tx];
                u64 bp0 = pk2(bv.x, bv.y), bp1 = pk2(bv.z, bv.w);
                float av[4] = { a.x, a.y, a.z, a.w };
                #pragma unroll
                for (int i = 0; i < 4; i++) {
                    u64 ap = pk2(av[i], av[i]);
                    acco[i][0] = ffma2(ap, bp0, acco[i][0]);
                    acco[i][1] = ffma2(ap, bp1, acco[i][1]);
                }
            }
        }
        __syncthreads();
    }

    // Column partials of O = acc/li, summed over this thread's 4 rows
    float part[4];
    #pragma unroll
    for (int j = 0; j < 4; j++) part[j] = 0.f;
    #pragma unroll
    for (int i = 0; i < 4; i++) {
        float rinv = 1.f / li[i];
        float o0, o1, o2, o3;
        up2(acco[i][0], o0, o1);
        up2(acco[i][1], o2, o3);
        part[0] += o0 * rinv; part[1] += o1 * rinv;
        part[2] += o2 * rinv; part[3] += o3 * rinv;
    }

    // Block reduce over ty groups (reuse Pst as scratch)
    #pragma unroll
    for (int j = 0; j < 4; j++) Pst[ty*64 + 4*tx + j] = part[j];
    __syncthreads();
    if (tid < 64) {
        float s = 0.f;
        #pragma unroll
        for (int r = 0; r < 16; r++) s += Pst[r*64 + tid];
        Psum[((size_t)bh * QTILES + qt) * DH + tid] = s;
    }
}

// ---------------------------------------------------------------------------
// Kernel 3: reduce q-tile partials -> mean context
// ---------------------------------------------------------------------------
__global__ __launch_bounds__(256) void reduce_kernel()
{
    int idx = blockIdx.x * 256 + threadIdx.x;   // 0..4095
    int b = idx >> 10;
    int h = (idx >> 6) & 15;
    int d = idx & 63;
    int bh = b * NH + h;
    float s = 0.f;
    #pragma unroll
    for (int qt = 0; qt < QTILES; qt++)
        s += Psum[((size_t)bh * QTILES + qt) * DH + d];
    Mctx[idx] = s * (1.0f / T);
}

// ---------------------------------------------------------------------------
// Kernel 4: out[b,n] = Mctx[b,:] . Wo[n,:] + bo[n]
// ---------------------------------------------------------------------------
__global__ __launch_bounds__(256) void out_kernel(
    const float* __restrict__ Wo, const float* __restrict__ bo,
    float* __restrict__ out)
{
    int gw = (blockIdx.x * 256 + threadIdx.x) >> 5;
    int lane = threadIdx.x & 31;
    int b = gw >> 10;
    int n = gw & 1023;
    const float* __restrict__ wrow = Wo + (size_t)n * H;
    const float* __restrict__ mrow = Mctx + b * H;
    float s = 0.f;
    #pragma unroll 4
    for (int k = lane; k < H; k += 32) s += mrow[k] * wrow[k];
    #pragma unroll
    for (int d = 16; d; d >>= 1) s += __shfl_xor_sync(0xffffffffu, s, d);
    if (lane == 0) out[b * H + n] = s + bo[n];
}

// ---------------------------------------------------------------------------
extern "C" void kernel_launch(void* const* d_in, const int* in_sizes, int n_in,
                              void* d_out, int out_size)
{
    const float* x  = (const float*)d_in[0];
    const float* Wq = (const float*)d_in[1];
    const float* Wk = (const float*)d_in[2];
    const float* Wv = (const float*)d_in[3];
    const float* Wo = (const float*)d_in[4];
    const float* bo = (const float*)d_in[5];
    float* out = (float*)d_out;

    proj_kernel<<<dim3(64, 8, 3), 256>>>(x, Wq, Wk, Wv);
    attn_kernel<<<dim3(QTILES, BH), 256>>>();
    reduce_kernel<<<16, 256>>>();
    out_kernel<<<512, 256>>>(Wo, bo, out);
}

// round 4
// speedup vs baseline: 1.7044x; 1.3429x over previous
#include <cuda_runtime.h>
#include <cuda_bf16.h>
#include <cstdint>

#define B 4
#define T 2048
#define H 1024
#define NH 16
#define DH 64
#define BH (B*NH)
#define QTILES (T/64)

typedef unsigned long long u64;

// ---------------- packed f32x2 helpers (attention) ----------------
__device__ __forceinline__ u64 pk2(float lo, float hi) {
    u64 r; asm("mov.b64 %0,{%1,%2};" : "=l"(r) : "f"(lo), "f"(hi)); return r;
}
__device__ __forceinline__ void up2(u64 v, float& lo, float& hi) {
    asm("mov.b64 {%0,%1},%2;" : "=f"(lo), "=f"(hi) : "l"(v));
}
__device__ __forceinline__ u64 ffma2(u64 a, u64 b, u64 c) {
    u64 d; asm("fma.rn.f32x2 %0,%1,%2,%3;" : "=l"(d) : "l"(a), "l"(b), "l"(c)); return d;
}
__device__ __forceinline__ u64 fmul2(u64 a, u64 b) {
    u64 d; asm("mul.rn.f32x2 %0,%1,%2;" : "=l"(d) : "l"(a), "l"(b)); return d;
}

// ---------------- mma.sync helpers (baseline ISA, compiles for compute_103) --
__device__ __forceinline__ uint32_t smem_u32(const void* p) {
    uint32_t a;
    asm("{ .reg .u64 t; cvta.to.shared.u64 t, %1; cvt.u32.u64 %0, t; }" : "=r"(a) : "l"(p));
    return a;
}
__device__ __forceinline__ void ldsm_x4(uint32_t& r0, uint32_t& r1, uint32_t& r2,
                                        uint32_t& r3, uint32_t addr) {
    asm volatile("ldmatrix.sync.aligned.m8n8.x4.shared.b16 {%0,%1,%2,%3}, [%4];"
                 : "=r"(r0), "=r"(r1), "=r"(r2), "=r"(r3) : "r"(addr));
}
__device__ __forceinline__ void mma_bf16(float* d, const uint32_t* a, const uint32_t* b) {
    asm volatile("mma.sync.aligned.m16n8k16.row.col.f32.bf16.bf16.f32 "
        "{%0,%1,%2,%3}, {%4,%5,%6,%7}, {%8,%9}, {%0,%1,%2,%3};"
        : "+f"(d[0]), "+f"(d[1]), "+f"(d[2]), "+f"(d[3])
        : "r"(a[0]), "r"(a[1]), "r"(a[2]), "r"(a[3]), "r"(b[0]), "r"(b[1]));
}
__device__ __forceinline__ void cp16(uint32_t saddr, const void* g) {
    asm volatile("cp.async.cg.shared.global [%0], [%1], 16;" :: "r"(saddr), "l"(g));
}
#define CP_COMMIT() asm volatile("cp.async.commit_group;" ::: "memory")
#define CP_WAIT0()  asm volatile("cp.async.wait_group 0;" ::: "memory")

// ---------------- scratch ----------------
__device__ float Qg[BH * T * DH];
__device__ float Kg[BH * T * DH];
__device__ float Vg[BH * T * DH];
__device__ float Psum[BH * QTILES * DH];
__device__ float Mctx[B * H];
__device__ __nv_bfloat16 Xh[(size_t)B * T * H];
__device__ __nv_bfloat16 Xl[(size_t)B * T * H];
__device__ __nv_bfloat16 Whg[3 * H * H];
__device__ __nv_bfloat16 Wlg[3 * H * H];

// ---------------------------------------------------------------------------
// Convert kernels: fp32 -> (bf16 hi, bf16 lo)
// ---------------------------------------------------------------------------
__global__ __launch_bounds__(256) void convert_x_kernel(const float* __restrict__ x)
{
    int i = blockIdx.x * 256 + threadIdx.x;
    float4 v = ((const float4*)x)[i];
    float a[4] = { v.x, v.y, v.z, v.w };
    #pragma unroll
    for (int j = 0; j < 4; j++) {
        __nv_bfloat16 hi = __float2bfloat16(a[j]);
        __nv_bfloat16 lo = __float2bfloat16(a[j] - __bfloat162float(hi));
        Xh[(size_t)i*4 + j] = hi;
        Xl[(size_t)i*4 + j] = lo;
    }
}

__global__ __launch_bounds__(256) void convert_w_kernel(const float* __restrict__ w, int which)
{
    int i = blockIdx.x * 256 + threadIdx.x;
    float4 v = ((const float4*)w)[i];
    float a[4] = { v.x, v.y, v.z, v.w };
    size_t base = (size_t)which * H * H + (size_t)i * 4;
    #pragma unroll
    for (int j = 0; j < 4; j++) {
        __nv_bfloat16 hi = __float2bfloat16(a[j]);
        __nv_bfloat16 lo = __float2bfloat16(a[j] - __bfloat162float(hi));
        Whg[base + j] = hi;
        Wlg[base + j] = lo;
    }
}

// ---------------------------------------------------------------------------
// Kernel 1: projection GEMM on mma.sync bf16 (3-term split).
// Block 128x128, K-stage 64, 8 warps (4m x 2n), warp tile 32x64.
// 2-stage cp.async pipeline. grid = (64, 8, 3).
// ---------------------------------------------------------------------------
#define BKP 64
#define NSTG (H / BKP)            // 16
#define TILE_B (128 * 128)        // 16KB: one 128-row x 128B tile
#define AH_OFF 0
#define AL_OFF (TILE_B)
#define BH_OFF (2 * TILE_B)
#define BL_OFF (3 * TILE_B)
#define STAGE_B (4 * TILE_B)      // 64KB
#define PROJ_SMEM (2 * STAGE_B + 1024)

// swizzled byte offset of 16B chunk c (0..7) in row r of a 128B-row tile
__device__ __forceinline__ uint32_t swz_off(int r, int c) {
    return (uint32_t)(r * 128 + ((c ^ (r & 7)) << 4));
}

__global__ __launch_bounds__(256) void proj_mma_kernel()
{
    extern __shared__ char dsm[];
    char* smp = (char*)(((uintptr_t)dsm + 1023) & ~(uintptr_t)1023);
    const uint32_t sb = smem_u32(smp);

    const int which = blockIdx.z;
    const int m0 = blockIdx.x * 128;
    const int n0 = blockIdx.y * 128;
    const int tid = threadIdx.x;
    const int wid = tid >> 5;
    const int lane = tid & 31;
    const int wm = wid & 3;        // warp m: 0..3  (32 rows)
    const int wn = wid >> 2;       // warp n: 0..1  (64 cols)

    const char* __restrict__ XhB = (const char*)Xh;
    const char* __restrict__ XlB = (const char*)Xl;
    const char* __restrict__ WhB = (const char*)(Whg + (size_t)which * H * H);
    const char* __restrict__ WlB = (const char*)(Wlg + (size_t)which * H * H);
    float* __restrict__ Og = (which == 0) ? Qg : (which == 1) ? Kg : Vg;

    float acc[2][8][4];
    #pragma unroll
    for (int i = 0; i < 2; i++)
        #pragma unroll
        for (int j = 0; j < 8; j++)
            #pragma unroll
            for (int q = 0; q < 4; q++) acc[i][j][q] = 0.f;

    // loader indices: 1024 chunks per tile, 4 per thread
    const int lr = tid >> 1;             // 0..127 (row, 2 chunks apart? no)
    // each thread loads 4 chunks per tile: idx = tid + 256*it; row = idx>>3, c = idx&7
    auto issue_stage = [&](int i) {
        const int k0 = i * BKP;
        const uint32_t st = sb + (i & 1) * STAGE_B;
        #pragma unroll
        for (int it = 0; it < 4; it++) {
            int idx = tid + 256 * it;
            int r = idx >> 3, c = idx & 7;
            uint32_t so = swz_off(r, c);
            size_t ga = ((size_t)(m0 + r) * H + k0) * 2 + c * 16;
            size_t gb = ((size_t)(n0 + r) * H + k0) * 2 + c * 16;
            cp16(st + AH_OFF + so, XhB + ga);
            cp16(st + AL_OFF + so, XlB + ga);
            cp16(st + BH_OFF + so, WhB + gb);
            cp16(st + BL_OFF + so, WlB + gb);
        }
        CP_COMMIT();
    };
    (void)lr;

    issue_stage(0);

    for (int i = 0; i < NSTG; i++) {
        CP_WAIT0();
        __syncthreads();
        if (i + 1 < NSTG) issue_stage(i + 1);

        const uint32_t st = sb + (i & 1) * STAGE_B;

        #pragma unroll
        for (int k16 = 0; k16 < 4; k16++) {
            // A fragments (hi, lo) for 2 m-tiles
            uint32_t ah[2][4], al[2][4];
            #pragma unroll
            for (int mt = 0; mt < 2; mt++) {
                int row = wm * 32 + mt * 16 + (lane & 15);
                int chunk = k16 * 2 + (lane >> 4);
                uint32_t so = swz_off(row, chunk);
                ldsm_x4(ah[mt][0], ah[mt][1], ah[mt][2], ah[mt][3], st + AH_OFF + so);
                ldsm_x4(al[mt][0], al[mt][1], al[mt][2], al[mt][3], st + AL_OFF + so);
            }
            // B fragments per n16 tile
            #pragma unroll
            for (int nt = 0; nt < 4; nt++) {
                int mat = lane >> 3, rin = lane & 7;
                int nrow = wn * 64 + nt * 16 + (mat >> 1) * 8 + rin;
                int chunk = k16 * 2 + (mat & 1);
                uint32_t so = swz_off(nrow, chunk);
                uint32_t bh0, bh1, bh2, bh3, bl0, bl1, bl2, bl3;
                ldsm_x4(bh0, bh1, bh2, bh3, st + BH_OFF + so);
                ldsm_x4(bl0, bl1, bl2, bl3, st + BL_OFF + so);
                uint32_t bhf[2][2] = { {bh0, bh1}, {bh2, bh3} };
                uint32_t blf[2][2] = { {bl0, bl1}, {bl2, bl3} };
                #pragma unroll
                for (int mt = 0; mt < 2; mt++) {
                    #pragma unroll
                    for (int j = 0; j < 2; j++) {
                        float* d = acc[mt][nt * 2 + j];
                        mma_bf16(d, ah[mt], bhf[j]);   // hi*hi
                        mma_bf16(d, ah[mt], blf[j]);   // hi*lo
                        mma_bf16(d, al[mt], bhf[j]);   // lo*hi
                    }
                }
            }
        }
        __syncthreads();
    }

    // Epilogue: head-split fp32 store
    #pragma unroll
    for (int mt = 0; mt < 2; mt++) {
        int row0 = m0 + wm * 32 + mt * 16 + (lane >> 2);
        #pragma unroll
        for (int nf = 0; nf < 8; nf++) {
            int col = n0 + wn * 64 + nf * 8 + 2 * (lane & 3);
            int h0 = col >> 6, d0 = col & 63;
            #pragma unroll
            for (int half = 0; half < 2; half++) {
                int m = row0 + half * 8;
                int b = m >> 11, t = m & 2047;
                float2 v = make_float2(acc[mt][nf][half*2], acc[mt][nf][half*2+1]);
                *(float2*)(Og + ((size_t)(b * NH + h0) * T + t) * DH + d0) = v;
            }
        }
    }
}

// ---------------------------------------------------------------------------
// Kernel 2: flash attention (unchanged from R2, FFMA2)
// ---------------------------------------------------------------------------
__device__ __forceinline__ int swz(int r, int c) { return (c + (r & ~3)) & 63; }

__global__ __launch_bounds__(256) void attn_kernel()
{
    __shared__ float Qst[64 * 64];
    __shared__ float Kv[64 * 64];
    __shared__ float Pst[64 * 64];

    const int qt = blockIdx.x;
    const int bh = blockIdx.y;
    const float* __restrict__ Qp = Qg + (size_t)bh * T * DH;
    const float* __restrict__ Kp = Kg + (size_t)bh * T * DH;
    const float* __restrict__ Vp = Vg + (size_t)bh * T * DH;

    const int tid = threadIdx.x;
    const int tx = tid & 15, ty = tid >> 4;
    const int q0 = qt * 64;

    #pragma unroll
    for (int j = 0; j < 4; j++) {
        int idx = tid + 256 * j;
        int r = idx >> 4;
        int kc = (idx & 15) * 4;
        float4 v = *(const float4*)(Qp + (size_t)(q0 + r) * DH + kc);
        Qst[(kc+0)*64 + swz(kc+0, r)] = v.x;
        Qst[(kc+1)*64 + swz(kc+1, r)] = v.y;
        Qst[(kc+2)*64 + swz(kc+2, r)] = v.z;
        Qst[(kc+3)*64 + swz(kc+3, r)] = v.w;
    }

    float mi[4], li[4];
    u64 accs[4][2], acco[4][2];
    #pragma unroll
    for (int i = 0; i < 4; i++) {
        mi[i] = -1e30f; li[i] = 0.f;
        accs[i][0] = accs[i][1] = 0ull;
        acco[i][0] = acco[i][1] = 0ull;
    }

    for (int s0 = 0; s0 < T; s0 += 64) {
        #pragma unroll
        for (int j = 0; j < 4; j++) {
            int idx = tid + 256 * j;
            int r = idx >> 4;
            int kc = (idx & 15) * 4;
            float4 v = *(const float4*)(Kp + (size_t)(s0 + r) * DH + kc);
            Kv[(kc+0)*64 + swz(kc+0, r)] = v.x;
            Kv[(kc+1)*64 + swz(kc+1, r)] = v.y;
            Kv[(kc+2)*64 + swz(kc+2, r)] = v.z;
            Kv[(kc+3)*64 + swz(kc+3, r)] = v.w;
        }
        __syncthreads();

        #pragma unroll
        for (int i = 0; i < 4; i++) { accs[i][0] = 0ull; accs[i][1] = 0ull; }
        for (int d0 = 0; d0 < 64; d0 += 4) {
            int qb = (4*ty + d0) & 63;
            int kb = (4*tx + d0) & 63;
            #pragma unroll
            for (int dd = 0; dd < 4; dd++) {
                int d = d0 + dd;
                float4 a = *(const float4*)&Qst[d*64 + qb];
                float4 bv = *(const float4*)&Kv[d*64 + kb];
                u64 bp0 = pk2(bv.x, bv.y), bp1 = pk2(bv.z, bv.w);
                float av[4] = { a.x, a.y, a.z, a.w };
                #pragma unroll
                for (int i = 0; i < 4; i++) {
                    u64 ap = pk2(av[i], av[i]);
                    accs[i][0] = ffma2(ap, bp0, accs[i][0]);
                    accs[i][1] = ffma2(ap, bp1, accs[i][1]);
                }
            }
        }

        #pragma unroll
        for (int i = 0; i < 4; i++) {
            float x0, x1, x2, x3;
            up2(accs[i][0], x0, x1);
            up2(accs[i][1], x2, x3);
            x0 *= 0.125f; x1 *= 0.125f; x2 *= 0.125f; x3 *= 0.125f;
            float mloc = fmaxf(fmaxf(x0, x1), fmaxf(x2, x3));
            #pragma unroll
            for (int msk = 1; msk < 16; msk <<= 1)
                mloc = fmaxf(mloc, __shfl_xor_sync(0xffffffffu, mloc, msk));
            float mn = fmaxf(mi[i], mloc);
            float p0 = __expf(x0 - mn), p1 = __expf(x1 - mn);
            float p2 = __expf(x2 - mn), p3 = __expf(x3 - mn);
            float alpha = __expf(mi[i] - mn);
            float rs = (p0 + p1) + (p2 + p3);
            #pragma unroll
            for (int msk = 1; msk < 16; msk <<= 1)
                rs += __shfl_xor_sync(0xffffffffu, rs, msk);
            li[i] = li[i] * alpha + rs;
            mi[i] = mn;
            u64 al2 = pk2(alpha, alpha);
            acco[i][0] = fmul2(acco[i][0], al2);
            acco[i][1] = fmul2(acco[i][1], al2);
            int col = (4*ty + i + 4*tx) & 63;
            Pst[(4*tx+0)*64 + col] = p0;
            Pst[(4*tx+1)*64 + col] = p1;
            Pst[(4*tx+2)*64 + col] = p2;
            Pst[(4*tx+3)*64 + col] = p3;
        }
        __syncthreads();

        #pragma unroll
        for (int j = 0; j < 4; j++) {
            int idx = tid + 256 * j;
            int r = idx >> 4;
            int kc = (idx & 15) * 4;
            float4 v = *(const float4*)(Vp + (size_t)(s0 + r) * DH + kc);
            *(float4*)&Kv[r*64 + kc] = v;
        }
        __syncthreads();

        for (int sb = 0; sb < 64; sb += 4) {
            int pb = (4*ty + sb) & 63;
            #pragma unroll
            for (int ss = 0; ss < 4; ss++) {
                int s = sb + ss;
                float4 a = *(const float4*)&Pst[s*64 + pb];
                float4 bv = *(const float4*)&Kv[s*64 + 4*tx];
                u64 bp0 = pk2(bv.x, bv.y), bp1 = pk2(bv.z, bv.w);
                float av[4] = { a.x, a.y, a.z, a.w };
                #pragma unroll
                for (int i = 0; i < 4; i++) {
                    u64 ap = pk2(av[i], av[i]);
                    acco[i][0] = ffma2(ap, bp0, acco[i][0]);
                    acco[i][1] = ffma2(ap, bp1, acco[i][1]);
                }
            }
        }
        __syncthreads();
    }

    float part[4];
    #pragma unroll
    for (int j = 0; j < 4; j++) part[j] = 0.f;
    #pragma unroll
    for (int i = 0; i < 4; i++) {
        float rinv = 1.f / li[i];
        float o0, o1, o2, o3;
        up2(acco[i][0], o0, o1);
        up2(acco[i][1], o2, o3);
        part[0] += o0 * rinv; part[1] += o1 * rinv;
        part[2] += o2 * rinv; part[3] += o3 * rinv;
    }

    #pragma unroll
    for (int j = 0; j < 4; j++) Pst[ty*64 + 4*tx + j] = part[j];
    __syncthreads();
    if (tid < 64) {
        float s = 0.f;
        #pragma unroll
        for (int r = 0; r < 16; r++) s += Pst[r*64 + tid];
        Psum[((size_t)bh * QTILES + qt) * DH + tid] = s;
    }
}

// ---------------------------------------------------------------------------
// Kernel 3 & 4 (unchanged)
// ---------------------------------------------------------------------------
__global__ __launch_bounds__(256) void reduce_kernel()
{
    int idx = blockIdx.x * 256 + threadIdx.x;
    int b = idx >> 10;
    int h = (idx >> 6) & 15;
    int d = idx & 63;
    int bh = b * NH + h;
    float s = 0.f;
    #pragma unroll
    for (int qt = 0; qt < QTILES; qt++)
        s += Psum[((size_t)bh * QTILES + qt) * DH + d];
    Mctx[idx] = s * (1.0f / T);
}

__global__ __launch_bounds__(256) void out_kernel(
    const float* __restrict__ Wo, const float* __restrict__ bo,
    float* __restrict__ out)
{
    int gw = (blockIdx.x * 256 + threadIdx.x) >> 5;
    int lane = threadIdx.x & 31;
    int b = gw >> 10;
    int n = gw & 1023;
    const float* __restrict__ wrow = Wo + (size_t)n * H;
    const float* __restrict__ mrow = Mctx + b * H;
    float s = 0.f;
    #pragma unroll 4
    for (int k = lane; k < H; k += 32) s += mrow[k] * wrow[k];
    #pragma unroll
    for (int d = 16; d; d >>= 1) s += __shfl_xor_sync(0xffffffffu, s, d);
    if (lane == 0) out[b * H + n] = s + bo[n];
}

// ---------------------------------------------------------------------------
extern "C" void kernel_launch(void* const* d_in, const int* in_sizes, int n_in,
                              void* d_out, int out_size)
{
    const float* x  = (const float*)d_in[0];
    const float* Wq = (const float*)d_in[1];
    const float* Wk = (const float*)d_in[2];
    const float* Wv = (const float*)d_in[3];
    const float* Wo = (const float*)d_in[4];
    const float* bo = (const float*)d_in[5];
    float* out = (float*)d_out;

    cudaFuncSetAttribute(proj_mma_kernel,
                         cudaFuncAttributeMaxDynamicSharedMemorySize, PROJ_SMEM);

    convert_x_kernel<<<(B*T*H)/(256*4), 256>>>(x);
    convert_w_kernel<<<(H*H)/(256*4), 256>>>(Wq, 0);
    convert_w_kernel<<<(H*H)/(256*4), 256>>>(Wk, 1);
    convert_w_kernel<<<(H*H)/(256*4), 256>>>(Wv, 2);
    proj_mma_kernel<<<dim3(64, 8, 3), 256, PROJ_SMEM>>>();
    attn_kernel<<<dim3(QTILES, BH), 256>>>();
    reduce_kernel<<<16, 256>>>();
    out_kernel<<<512, 256>>>(Wo, bo, out);
}

// round 6
// speedup vs baseline: 3.7952x; 2.2266x over previous
#include <cuda_runtime.h>
#include <cuda_bf16.h>
#include <cstdint>

#define B 4
#define T 2048
#define H 1024
#define NH 16
#define DH 64
#define BH (B*NH)
#define QT128 (T/128)     // 16 q-tiles of 128

// ---------------- mma.sync helpers (baseline ISA) ----------------
__device__ __forceinline__ uint32_t smem_u32(const void* p) {
    uint32_t a;
    asm("{ .reg .u64 t; cvta.to.shared.u64 t, %1; cvt.u32.u64 %0, t; }" : "=r"(a) : "l"(p));
    return a;
}
__device__ __forceinline__ void ldsm_x4(uint32_t& r0, uint32_t& r1, uint32_t& r2,
                                        uint32_t& r3, uint32_t addr) {
    asm volatile("ldmatrix.sync.aligned.m8n8.x4.shared.b16 {%0,%1,%2,%3}, [%4];"
                 : "=r"(r0), "=r"(r1), "=r"(r2), "=r"(r3) : "r"(addr));
}
__device__ __forceinline__ void ldsm_x4_t(uint32_t& r0, uint32_t& r1, uint32_t& r2,
                                          uint32_t& r3, uint32_t addr) {
    asm volatile("ldmatrix.sync.aligned.m8n8.x4.trans.shared.b16 {%0,%1,%2,%3}, [%4];"
                 : "=r"(r0), "=r"(r1), "=r"(r2), "=r"(r3) : "r"(addr));
}
__device__ __forceinline__ void mma_bf16(float* d, const uint32_t* a, const uint32_t* b) {
    asm volatile("mma.sync.aligned.m16n8k16.row.col.f32.bf16.bf16.f32 "
        "{%0,%1,%2,%3}, {%4,%5,%6,%7}, {%8,%9}, {%0,%1,%2,%3};"
        : "+f"(d[0]), "+f"(d[1]), "+f"(d[2]), "+f"(d[3])
        : "r"(a[0]), "r"(a[1]), "r"(a[2]), "r"(a[3]), "r"(b[0]), "r"(b[1]));
}
__device__ __forceinline__ void cp16(uint32_t saddr, const void* g) {
    asm volatile("cp.async.cg.shared.global [%0], [%1], 16;" :: "r"(saddr), "l"(g));
}
#define CP_COMMIT() asm volatile("cp.async.commit_group;" ::: "memory")
#define CP_WAIT0()  asm volatile("cp.async.wait_group 0;" ::: "memory")
#define CP_WAIT1()  asm volatile("cp.async.wait_group 1;" ::: "memory")

// swizzled byte offset of 16B chunk c (0..7) in row r of a 128B-row tile
__device__ __forceinline__ uint32_t swz_off(int r, int c) {
    return (uint32_t)(r * 128 + ((c ^ (r & 7)) << 4));
}

// ---------------- scratch ----------------
__device__ float Psum[BH * QT128 * DH];
__device__ float Mctx[B * H];
__device__ __nv_bfloat16 Xh[(size_t)B * T * H];
__device__ __nv_bfloat16 Xl[(size_t)B * T * H];
__device__ __nv_bfloat16 Whg[3 * H * H];
__device__ __nv_bfloat16 Wlg[3 * H * H];
// head-split bf16 hi/lo projections
__device__ __nv_bfloat16 QhG[(size_t)BH * T * DH];
__device__ __nv_bfloat16 QlG[(size_t)BH * T * DH];
__device__ __nv_bfloat16 KhG[(size_t)BH * T * DH];
__device__ __nv_bfloat16 KlG[(size_t)BH * T * DH];
__device__ __nv_bfloat16 VhG[(size_t)BH * T * DH];
__device__ __nv_bfloat16 VlG[(size_t)BH * T * DH];

// ---------------------------------------------------------------------------
// Convert kernels: fp32 -> (bf16 hi, bf16 lo)
// ---------------------------------------------------------------------------
__global__ __launch_bounds__(256) void convert_x_kernel(const float* __restrict__ x)
{
    int i = blockIdx.x * 256 + threadIdx.x;
    float4 v = ((const float4*)x)[i];
    float a[4] = { v.x, v.y, v.z, v.w };
    #pragma unroll
    for (int j = 0; j < 4; j++) {
        __nv_bfloat16 hi = __float2bfloat16(a[j]);
        __nv_bfloat16 lo = __float2bfloat16(a[j] - __bfloat162float(hi));
        Xh[(size_t)i*4 + j] = hi;
        Xl[(size_t)i*4 + j] = lo;
    }
}

__global__ __launch_bounds__(256) void convert_w_kernel(const float* __restrict__ w, int which)
{
    int i = blockIdx.x * 256 + threadIdx.x;
    float4 v = ((const float4*)w)[i];
    float a[4] = { v.x, v.y, v.z, v.w };
    size_t base = (size_t)which * H * H + (size_t)i * 4;
    #pragma unroll
    for (int j = 0; j < 4; j++) {
        __nv_bfloat16 hi = __float2bfloat16(a[j]);
        __nv_bfloat16 lo = __float2bfloat16(a[j] - __bfloat162float(hi));
        Whg[base + j] = hi;
        Wlg[base + j] = lo;
    }
}

// ---------------------------------------------------------------------------
// Kernel 1: projection GEMM (mma.sync, 3-term split), bf16 hi/lo output.
// ---------------------------------------------------------------------------
#define BKP 64
#define NSTG (H / BKP)
#define TILE_B (128 * 128)
#define AH_OFF 0
#define AL_OFF (TILE_B)
#define BHh_OFF (2 * TILE_B)
#define BLl_OFF (3 * TILE_B)
#define STAGE_B (4 * TILE_B)
#define PROJ_SMEM (2 * STAGE_B + 1024)

__global__ __launch_bounds__(256) void proj_mma_kernel()
{
    extern __shared__ char dsm[];
    char* smp = (char*)(((uintptr_t)dsm + 1023) & ~(uintptr_t)1023);
    const uint32_t sb = smem_u32(smp);

    const int which = blockIdx.z;
    const int m0 = blockIdx.x * 128;
    const int n0 = blockIdx.y * 128;
    const int tid = threadIdx.x;
    const int wid = tid >> 5;
    const int lane = tid & 31;
    const int wm = wid & 3;
    const int wn = wid >> 2;

    const char* __restrict__ XhB = (const char*)Xh;
    const char* __restrict__ XlB = (const char*)Xl;
    const char* __restrict__ WhB = (const char*)(Whg + (size_t)which * H * H);
    const char* __restrict__ WlB = (const char*)(Wlg + (size_t)which * H * H);
    __nv_bfloat16* __restrict__ OgH = (which == 0) ? QhG : (which == 1) ? KhG : VhG;
    __nv_bfloat16* __restrict__ OgL = (which == 0) ? QlG : (which == 1) ? KlG : VlG;

    float acc[2][8][4];
    #pragma unroll
    for (int i = 0; i < 2; i++)
        #pragma unroll
        for (int j = 0; j < 8; j++)
            #pragma unroll
            for (int q = 0; q < 4; q++) acc[i][j][q] = 0.f;

    auto issue_stage = [&](int i) {
        const int k0 = i * BKP;
        const uint32_t st = sb + (i & 1) * STAGE_B;
        #pragma unroll
        for (int it = 0; it < 4; it++) {
            int idx = tid + 256 * it;
            int r = idx >> 3, c = idx & 7;
            uint32_t so = swz_off(r, c);
            size_t ga = ((size_t)(m0 + r) * H + k0) * 2 + c * 16;
            size_t gb = ((size_t)(n0 + r) * H + k0) * 2 + c * 16;
            cp16(st + AH_OFF + so, XhB + ga);
            cp16(st + AL_OFF + so, XlB + ga);
            cp16(st + BHh_OFF + so, WhB + gb);
            cp16(st + BLl_OFF + so, WlB + gb);
        }
        CP_COMMIT();
    };

    issue_stage(0);

    for (int i = 0; i < NSTG; i++) {
        CP_WAIT0();
        __syncthreads();
        if (i + 1 < NSTG) issue_stage(i + 1);

        const uint32_t st = sb + (i & 1) * STAGE_B;

        #pragma unroll
        for (int k16 = 0; k16 < 4; k16++) {
            uint32_t ah[2][4], al[2][4];
            #pragma unroll
            for (int mt = 0; mt < 2; mt++) {
                int row = wm * 32 + mt * 16 + (lane & 15);
                int chunk = k16 * 2 + (lane >> 4);
                uint32_t so = swz_off(row, chunk);
                ldsm_x4(ah[mt][0], ah[mt][1], ah[mt][2], ah[mt][3], st + AH_OFF + so);
                ldsm_x4(al[mt][0], al[mt][1], al[mt][2], al[mt][3], st + AL_OFF + so);
            }
            #pragma unroll
            for (int nt = 0; nt < 4; nt++) {
                int mat = lane >> 3, rin = lane & 7;
                int nrow = wn * 64 + nt * 16 + (mat >> 1) * 8 + rin;
                int chunk = k16 * 2 + (mat & 1);
                uint32_t so = swz_off(nrow, chunk);
                uint32_t bh0, bh1, bh2, bh3, bl0, bl1, bl2, bl3;
                ldsm_x4(bh0, bh1, bh2, bh3, st + BHh_OFF + so);
                ldsm_x4(bl0, bl1, bl2, bl3, st + BLl_OFF + so);
                uint32_t bhf[2][2] = { {bh0, bh1}, {bh2, bh3} };
                uint32_t blf[2][2] = { {bl0, bl1}, {bl2, bl3} };
                #pragma unroll
                for (int mt = 0; mt < 2; mt++) {
                    #pragma unroll
                    for (int j = 0; j < 2; j++) {
                        float* d = acc[mt][nt * 2 + j];
                        mma_bf16(d, ah[mt], bhf[j]);
                        mma_bf16(d, ah[mt], blf[j]);
                        mma_bf16(d, al[mt], bhf[j]);
                    }
                }
            }
        }
        __syncthreads();
    }

    // Epilogue: bf16 hi/lo head-split store (Q scaled by 1/8)
    const float scale = (which == 0) ? 0.125f : 1.0f;
    #pragma unroll
    for (int mt = 0; mt < 2; mt++) {
        int row0 = m0 + wm * 32 + mt * 16 + (lane >> 2);
        #pragma unroll
        for (int nf = 0; nf < 8; nf++) {
            int col = n0 + wn * 64 + nf * 8 + 2 * (lane & 3);
            int h0 = col >> 6, d0 = col & 63;
            #pragma unroll
            for (int half = 0; half < 2; half++) {
                int m = row0 + half * 8;
                int b = m >> 11, t = m & 2047;
                float v0 = acc[mt][nf][half*2]   * scale;
                float v1 = acc[mt][nf][half*2+1] * scale;
                __nv_bfloat162 hh = __floats2bfloat162_rn(v0, v1);
                float r0 = v0 - __bfloat162float(hh.x);
                float r1 = v1 - __bfloat162float(hh.y);
                __nv_bfloat162 ll = __floats2bfloat162_rn(r0, r1);
                size_t off = ((size_t)(b * NH + h0) * T + t) * DH + d0;
                *(__nv_bfloat162*)(OgH + off) = hh;
                *(__nv_bfloat162*)(OgL + off) = ll;
            }
        }
    }
}

// ---------------------------------------------------------------------------
// Kernel 2: flash attention on mma.sync. 128 q-rows/CTA, 64-key tiles.
// grid = (QT128=16, BH=64), 256 threads (8 warps x 16 q-rows).
// ---------------------------------------------------------------------------
#define AT_KH 0
#define AT_KL 8192
#define AT_VH 16384
#define AT_VL 24576
#define AT_STAGE 32768
#define ATT_SMEM (2 * AT_STAGE + 1024)

__global__ __launch_bounds__(256) void attn_mma_kernel()
{
    extern __shared__ char dsm[];
    __shared__ float red[8][64];
    char* smp = (char*)(((uintptr_t)dsm + 1023) & ~(uintptr_t)1023);
    const uint32_t sb = smem_u32(smp);

    const int qt = blockIdx.x;
    const int bh = blockIdx.y;
    const int tid = threadIdx.x;
    const int wid = tid >> 5;
    const int lane = tid & 31;
    const int q0 = qt * 128;

    const char* __restrict__ QhP = (const char*)(QhG + (size_t)bh * T * DH);
    const char* __restrict__ QlP = (const char*)(QlG + (size_t)bh * T * DH);
    const char* __restrict__ KhP = (const char*)(KhG + (size_t)bh * T * DH);
    const char* __restrict__ KlP = (const char*)(KlG + (size_t)bh * T * DH);
    const char* __restrict__ VhP = (const char*)(VhG + (size_t)bh * T * DH);
    const char* __restrict__ VlP = (const char*)(VlG + (size_t)bh * T * DH);

    // ---- load Q tile (128 x 64 hi/lo) into stage0, extract A-frags ----
    #pragma unroll
    for (int it = 0; it < 4; it++) {
        int idx = tid + 256 * it;
        int r = idx >> 3, c = idx & 7;
        uint32_t so = swz_off(r, c);
        size_t g = (size_t)(q0 + r) * 128 + c * 16;
        cp16(sb + so, QhP + g);
        cp16(sb + 16384 + so, QlP + g);
    }
    CP_COMMIT();
    CP_WAIT0();
    __syncthreads();

    uint32_t qh[4][4], ql[4][4];
    #pragma unroll
    for (int k16 = 0; k16 < 4; k16++) {
        int row = wid * 16 + (lane & 15);
        int chunk = k16 * 2 + (lane >> 4);
        uint32_t so = swz_off(row, chunk);
        ldsm_x4(qh[k16][0], qh[k16][1], qh[k16][2], qh[k16][3], sb + so);
        ldsm_x4(ql[k16][0], ql[k16][1], ql[k16][2], ql[k16][3], sb + 16384 + so);
    }
    __syncthreads();

    // ---- KV pipeline ----
    auto issue_kv = [&](int i) {
        const int s0 = i * 64;
        const uint32_t st = sb + (i & 1) * AT_STAGE;
        #pragma unroll
        for (int it = 0; it < 2; it++) {
            int idx = tid + 256 * it;
            int r = idx >> 3, c = idx & 7;
            uint32_t so = swz_off(r, c);
            size_t g = (size_t)(s0 + r) * 128 + c * 16;
            cp16(st + AT_KH + so, KhP + g);
            cp16(st + AT_KL + so, KlP + g);
            cp16(st + AT_VH + so, VhP + g);
            cp16(st + AT_VL + so, VlP + g);
        }
        CP_COMMIT();
    };

    issue_kv(0);
    issue_kv(1);

    float m0 = -1e30f, m1 = -1e30f, l0 = 0.f, l1 = 0.f;
    float oacc[8][4];
    #pragma unroll
    for (int t = 0; t < 8; t++)
        #pragma unroll
        for (int q = 0; q < 4; q++) oacc[t][q] = 0.f;

    for (int i = 0; i < 32; i++) {
        if (i < 30) { CP_WAIT1(); } else { CP_WAIT0(); }
        __syncthreads();

        const uint32_t st = sb + (i & 1) * AT_STAGE;

        // ---- S = Q K^T (3-term) ----
        float sacc[8][4];
        #pragma unroll
        for (int t = 0; t < 8; t++)
            #pragma unroll
            for (int q = 0; q < 4; q++) sacc[t][q] = 0.f;

        #pragma unroll
        for (int k16 = 0; k16 < 4; k16++) {
            #pragma unroll
            for (int nt = 0; nt < 4; nt++) {
                int mat = lane >> 3, rin = lane & 7;
                int nrow = nt * 16 + (mat >> 1) * 8 + rin;
                int chunk = k16 * 2 + (mat & 1);
                uint32_t so = swz_off(nrow, chunk);
                uint32_t b0, b1, b2, b3, c0, c1, c2, c3;
                ldsm_x4(b0, b1, b2, b3, st + AT_KH + so);
                ldsm_x4(c0, c1, c2, c3, st + AT_KL + so);
                uint32_t bh01[2] = {b0, b1}, bh23[2] = {b2, b3};
                uint32_t bl01[2] = {c0, c1}, bl23[2] = {c2, c3};
                mma_bf16(sacc[2*nt],   qh[k16], bh01);
                mma_bf16(sacc[2*nt],   qh[k16], bl01);
                mma_bf16(sacc[2*nt],   ql[k16], bh01);
                mma_bf16(sacc[2*nt+1], qh[k16], bh23);
                mma_bf16(sacc[2*nt+1], qh[k16], bl23);
                mma_bf16(sacc[2*nt+1], ql[k16], bh23);
            }
        }

        // ---- online softmax (rows: r0 = lane>>2, r1 = r0+8) ----
        float ml0 = -1e30f, ml1 = -1e30f;
        #pragma unroll
        for (int t = 0; t < 8; t++) {
            ml0 = fmaxf(ml0, fmaxf(sacc[t][0], sacc[t][1]));
            ml1 = fmaxf(ml1, fmaxf(sacc[t][2], sacc[t][3]));
        }
        ml0 = fmaxf(ml0, __shfl_xor_sync(0xffffffffu, ml0, 1));
        ml0 = fmaxf(ml0, __shfl_xor_sync(0xffffffffu, ml0, 2));
        ml1 = fmaxf(ml1, __shfl_xor_sync(0xffffffffu, ml1, 1));
        ml1 = fmaxf(ml1, __shfl_xor_sync(0xffffffffu, ml1, 2));
        float mn0 = fmaxf(m0, ml0), mn1 = fmaxf(m1, ml1);

        float rs0 = 0.f, rs1 = 0.f;
        uint32_t phA[8], phB[8], plA[8], plB[8];
        #pragma unroll
        for (int t = 0; t < 8; t++) {
            float p0 = __expf(sacc[t][0] - mn0);
            float p1 = __expf(sacc[t][1] - mn0);
            float p2 = __expf(sacc[t][2] - mn1);
            float p3 = __expf(sacc[t][3] - mn1);
            rs0 += p0 + p1;
            rs1 += p2 + p3;
            __nv_bfloat162 hA = __floats2bfloat162_rn(p0, p1);
            __nv_bfloat162 hB = __floats2bfloat162_rn(p2, p3);
            __nv_bfloat162 lA = __floats2bfloat162_rn(p0 - __bfloat162float(hA.x),
                                                      p1 - __bfloat162float(hA.y));
            __nv_bfloat162 lB = __floats2bfloat162_rn(p2 - __bfloat162float(hB.x),
                                                      p3 - __bfloat162float(hB.y));
            phA[t] = *(uint32_t*)&hA;
            phB[t] = *(uint32_t*)&hB;
            plA[t] = *(uint32_t*)&lA;
            plB[t] = *(uint32_t*)&lB;
        }
        rs0 += __shfl_xor_sync(0xffffffffu, rs0, 1);
        rs0 += __shfl_xor_sync(0xffffffffu, rs0, 2);
        rs1 += __shfl_xor_sync(0xffffffffu, rs1, 1);
        rs1 += __shfl_xor_sync(0xffffffffu, rs1, 2);

        float a0 = __expf(m0 - mn0), a1 = __expf(m1 - mn1);
        l0 = l0 * a0 + rs0;
        l1 = l1 * a1 + rs1;
        m0 = mn0; m1 = mn1;
        #pragma unroll
        for (int t = 0; t < 8; t++) {
            oacc[t][0] *= a0; oacc[t][1] *= a0;
            oacc[t][2] *= a1; oacc[t][3] *= a1;
        }

        // ---- O += P V (3-term), V via ldmatrix.trans ----
        #pragma unroll
        for (int j = 0; j < 4; j++) {
            uint32_t Ah[4] = { phA[2*j], phB[2*j], phA[2*j+1], phB[2*j+1] };
            uint32_t Al[4] = { plA[2*j], plB[2*j], plA[2*j+1], plB[2*j+1] };
            #pragma unroll
            for (int tt = 0; tt < 8; tt += 2) {
                int mi = lane >> 3;
                int row = 16*j + (mi & 1) * 8 + (lane & 7);
                int chunk = tt + (mi >> 1);
                uint32_t so = swz_off(row, chunk);
                uint32_t b0, b1, b2, b3, c0, c1, c2, c3;
                ldsm_x4_t(b0, b1, b2, b3, st + AT_VH + so);
                ldsm_x4_t(c0, c1, c2, c3, st + AT_VL + so);
                uint32_t bh01[2] = {b0, b1}, bh23[2] = {b2, b3};
                uint32_t bl01[2] = {c0, c1}, bl23[2] = {c2, c3};
                mma_bf16(oacc[tt],   Ah, bh01);
                mma_bf16(oacc[tt],   Ah, bl01);
                mma_bf16(oacc[tt],   Al, bh01);
                mma_bf16(oacc[tt+1], Ah, bh23);
                mma_bf16(oacc[tt+1], Ah, bl23);
                mma_bf16(oacc[tt+1], Al, bh23);
            }
        }
        __syncthreads();
        if (i + 2 < 32) issue_kv(i + 2);
    }

    // ---- column sums of O/l over this warp's 16 rows ----
    float inv0 = 1.f / l0, inv1 = 1.f / l1;
    float cp0[8], cp1[8];
    #pragma unroll
    for (int t = 0; t < 8; t++) {
        cp0[t] = oacc[t][0] * inv0 + oacc[t][2] * inv1;
        cp1[t] = oacc[t][1] * inv0 + oacc[t][3] * inv1;
    }
    #pragma unroll
    for (int msk = 4; msk < 32; msk <<= 1) {
        #pragma unroll
        for (int t = 0; t < 8; t++) {
            cp0[t] += __shfl_xor_sync(0xffffffffu, cp0[t], msk);
            cp1[t] += __shfl_xor_sync(0xffffffffu, cp1[t], msk);
        }
    }
    if ((lane >> 2) == 0) {
        #pragma unroll
        for (int t = 0; t < 8; t++) {
            red[wid][8*t + 2*lane + 0] = cp0[t];
            red[wid][8*t + 2*lane + 1] = cp1[t];
        }
    }
    __syncthreads();
    if (tid < 64) {
        float s = 0.f;
        #pragma unroll
        for (int w = 0; w < 8; w++) s += red[w][tid];
        Psum[((size_t)bh * QT128 + qt) * DH + tid] = s;
    }
}

// ---------------------------------------------------------------------------
// Kernel 3 & 4
// ---------------------------------------------------------------------------
__global__ __launch_bounds__(256) void reduce_kernel()
{
    int idx = blockIdx.x * 256 + threadIdx.x;
    int b = idx >> 10;
    int h = (idx >> 6) & 15;
    int d = idx & 63;
    int bh = b * NH + h;
    float s = 0.f;
    #pragma unroll
    for (int qt = 0; qt < QT128; qt++)
        s += Psum[((size_t)bh * QT128 + qt) * DH + d];
    Mctx[idx] = s * (1.0f / T);
}

__global__ __launch_bounds__(256) void out_kernel(
    const float* __restrict__ Wo, const float* __restrict__ bo,
    float* __restrict__ out)
{
    int gw = (blockIdx.x * 256 + threadIdx.x) >> 5;
    int lane = threadIdx.x & 31;
    int b = gw >> 10;
    int n = gw & 1023;
    const float* __restrict__ wrow = Wo + (size_t)n * H;
    const float* __restrict__ mrow = Mctx + b * H;
    float s = 0.f;
    #pragma unroll 4
    for (int k = lane; k < H; k += 32) s += mrow[k] * wrow[k];
    #pragma unroll
    for (int d = 16; d; d >>= 1) s += __shfl_xor_sync(0xffffffffu, s, d);
    if (lane == 0) out[b * H + n] = s + bo[n];
}

// ---------------------------------------------------------------------------
extern "C" void kernel_launch(void* const* d_in, const int* in_sizes, int n_in,
                              void* d_out, int out_size)
{
    const float* x  = (const float*)d_in[0];
    const float* Wq = (const float*)d_in[1];
    const float* Wk = (const float*)d_in[2];
    const float* Wv = (const float*)d_in[3];
    const float* Wo = (const float*)d_in[4];
    const float* bo = (const float*)d_in[5];
    float* out = (float*)d_out;

    cudaFuncSetAttribute(proj_mma_kernel,
                         cudaFuncAttributeMaxDynamicSharedMemorySize, PROJ_SMEM);
    cudaFuncSetAttribute(attn_mma_kernel,
                         cudaFuncAttributeMaxDynamicSharedMemorySize, ATT_SMEM);

    convert_x_kernel<<<(B*T*H)/(256*4), 256>>>(x);
    convert_w_kernel<<<(H*H)/(256*4), 256>>>(Wq, 0);
    convert_w_kernel<<<(H*H)/(256*4), 256>>>(Wk, 1);
    convert_w_kernel<<<(H*H)/(256*4), 256>>>(Wv, 2);
    proj_mma_kernel<<<dim3(64, 8, 3), 256, PROJ_SMEM>>>();
    attn_mma_kernel<<<dim3(QT128, BH), 256, ATT_SMEM>>>();
    reduce_kernel<<<16, 256>>>();
    out_kernel<<<512, 256>>>(Wo, bo, out);
}

// round 7
// speedup vs baseline: 7.5010x; 1.9765x over previous
#include <cuda_runtime.h>
#include <cuda_fp16.h>
#include <cstdint>

#define B 4
#define T 2048
#define H 1024
#define NH 16
#define DH 64
#define BH (B*NH)
#define QT128 (T/128)     // 16 q-tiles of 128

// ---------------- mma.sync helpers (baseline ISA) ----------------
__device__ __forceinline__ uint32_t smem_u32(const void* p) {
    uint32_t a;
    asm("{ .reg .u64 t; cvta.to.shared.u64 t, %1; cvt.u32.u64 %0, t; }" : "=r"(a) : "l"(p));
    return a;
}
__device__ __forceinline__ void ldsm_x4(uint32_t& r0, uint32_t& r1, uint32_t& r2,
                                        uint32_t& r3, uint32_t addr) {
    asm volatile("ldmatrix.sync.aligned.m8n8.x4.shared.b16 {%0,%1,%2,%3}, [%4];"
                 : "=r"(r0), "=r"(r1), "=r"(r2), "=r"(r3) : "r"(addr));
}
__device__ __forceinline__ void ldsm_x4_t(uint32_t& r0, uint32_t& r1, uint32_t& r2,
                                          uint32_t& r3, uint32_t addr) {
    asm volatile("ldmatrix.sync.aligned.m8n8.x4.trans.shared.b16 {%0,%1,%2,%3}, [%4];"
                 : "=r"(r0), "=r"(r1), "=r"(r2), "=r"(r3) : "r"(addr));
}
__device__ __forceinline__ void mma_f16(float* d, const uint32_t* a, const uint32_t* b) {
    asm volatile("mma.sync.aligned.m16n8k16.row.col.f32.f16.f16.f32 "
        "{%0,%1,%2,%3}, {%4,%5,%6,%7}, {%8,%9}, {%0,%1,%2,%3};"
        : "+f"(d[0]), "+f"(d[1]), "+f"(d[2]), "+f"(d[3])
        : "r"(a[0]), "r"(a[1]), "r"(a[2]), "r"(a[3]), "r"(b[0]), "r"(b[1]));
}
__device__ __forceinline__ void cp16(uint32_t saddr, const void* g) {
    asm volatile("cp.async.cg.shared.global [%0], [%1], 16;" :: "r"(saddr), "l"(g));
}
#define CP_COMMIT() asm volatile("cp.async.commit_group;" ::: "memory")
#define CP_WAIT0()  asm volatile("cp.async.wait_group 0;" ::: "memory")
#define CP_WAIT1()  asm volatile("cp.async.wait_group 1;" ::: "memory")

// swizzled byte offset of 16B chunk c (0..7) in row r of a 128B-row tile
__device__ __forceinline__ uint32_t swz_off(int r, int c) {
    return (uint32_t)(r * 128 + ((c ^ (r & 7)) << 4));
}

// ---------------- scratch ----------------
__device__ float Psum[BH * QT128 * DH];
__device__ float Mctx[B * H];
__device__ __half Xh[(size_t)B * T * H];      // x hi (fp16)
__device__ __half Xl[(size_t)B * T * H];      // x lo (fp16)
__device__ __half Whg[3 * H * H];             // W single fp16
__device__ __half QhG[(size_t)BH * T * DH];   // Q single fp16 (pre-scaled by 1/8)
__device__ __half KhG[(size_t)BH * T * DH];   // K single fp16
__device__ __half VhG[(size_t)BH * T * DH];   // V single fp16

// ---------------------------------------------------------------------------
// Convert kernels
// ---------------------------------------------------------------------------
__global__ __launch_bounds__(256) void convert_x_kernel(const float* __restrict__ x)
{
    int i = blockIdx.x * 256 + threadIdx.x;
    float4 v = ((const float4*)x)[i];
    float a[4] = { v.x, v.y, v.z, v.w };
    __half hs[4], ls[4];
    #pragma unroll
    for (int j = 0; j < 4; j++) {
        __half hi = __float2half_rn(a[j]);
        hs[j] = hi;
        ls[j] = __float2half_rn(a[j] - __half2float(hi));
    }
    *(uint2*)(Xh + (size_t)i*4) = *(uint2*)hs;
    *(uint2*)(Xl + (size_t)i*4) = *(uint2*)ls;
}

__global__ __launch_bounds__(256) void convert_w_kernel(
    const float* __restrict__ Wq, const float* __restrict__ Wk,
    const float* __restrict__ Wv)
{
    const float* w = (blockIdx.y == 0) ? Wq : (blockIdx.y == 1) ? Wk : Wv;
    int i = blockIdx.x * 256 + threadIdx.x;
    float4 v = ((const float4*)w)[i];
    __half hs[4] = { __float2half_rn(v.x), __float2half_rn(v.y),
                     __float2half_rn(v.z), __float2half_rn(v.w) };
    *(uint2*)(Whg + (size_t)blockIdx.y * H * H + (size_t)i*4) = *(uint2*)hs;
}

// ---------------------------------------------------------------------------
// Kernel 1: projection GEMM (mma.sync fp16, 2-term x-split).
// Block 128x128, K-stage 64, 8 warps (4m x 2n). grid = (64, 8, 3).
// ---------------------------------------------------------------------------
#define BKP 64
#define NSTG (H / BKP)
#define TILE_B (128 * 128)        // 16KB tile (128 rows x 64 fp16)
#define AH_OFF 0
#define AL_OFF (TILE_B)
#define BW_OFF (2 * TILE_B)
#define STAGE_B (3 * TILE_B)      // 48KB
#define PROJ_SMEM (2 * STAGE_B + 1024)

__global__ __launch_bounds__(256) void proj_mma_kernel()
{
    extern __shared__ char dsm[];
    char* smp = (char*)(((uintptr_t)dsm + 1023) & ~(uintptr_t)1023);
    const uint32_t sb = smem_u32(smp);

    const int which = blockIdx.z;
    const int m0 = blockIdx.x * 128;
    const int n0 = blockIdx.y * 128;
    const int tid = threadIdx.x;
    const int wid = tid >> 5;
    const int lane = tid & 31;
    const int wm = wid & 3;
    const int wn = wid >> 2;

    const char* __restrict__ XhB = (const char*)Xh;
    const char* __restrict__ XlB = (const char*)Xl;
    const char* __restrict__ WB  = (const char*)(Whg + (size_t)which * H * H);
    __half* __restrict__ Og = (which == 0) ? QhG : (which == 1) ? KhG : VhG;

    float acc[2][8][4];
    #pragma unroll
    for (int i = 0; i < 2; i++)
        #pragma unroll
        for (int j = 0; j < 8; j++)
            #pragma unroll
            for (int q = 0; q < 4; q++) acc[i][j][q] = 0.f;

    auto issue_stage = [&](int i) {
        const int k0 = i * BKP;
        const uint32_t st = sb + (i & 1) * STAGE_B;
        #pragma unroll
        for (int it = 0; it < 4; it++) {
            int idx = tid + 256 * it;
            int r = idx >> 3, c = idx & 7;
            uint32_t so = swz_off(r, c);
            size_t ga = ((size_t)(m0 + r) * H + k0) * 2 + c * 16;
            size_t gb = ((size_t)(n0 + r) * H + k0) * 2 + c * 16;
            cp16(st + AH_OFF + so, XhB + ga);
            cp16(st + AL_OFF + so, XlB + ga);
            cp16(st + BW_OFF + so, WB + gb);
        }
        CP_COMMIT();
    };

    issue_stage(0);

    for (int i = 0; i < NSTG; i++) {
        CP_WAIT0();
        __syncthreads();
        if (i + 1 < NSTG) issue_stage(i + 1);

        const uint32_t st = sb + (i & 1) * STAGE_B;

        #pragma unroll
        for (int k16 = 0; k16 < 4; k16++) {
            uint32_t ah[2][4], al[2][4];
            #pragma unroll
            for (int mt = 0; mt < 2; mt++) {
                int row = wm * 32 + mt * 16 + (lane & 15);
                int chunk = k16 * 2 + (lane >> 4);
                uint32_t so = swz_off(row, chunk);
                ldsm_x4(ah[mt][0], ah[mt][1], ah[mt][2], ah[mt][3], st + AH_OFF + so);
                ldsm_x4(al[mt][0], al[mt][1], al[mt][2], al[mt][3], st + AL_OFF + so);
            }
            #pragma unroll
            for (int nt = 0; nt < 4; nt++) {
                int mat = lane >> 3, rin = lane & 7;
                int nrow = wn * 64 + nt * 16 + (mat >> 1) * 8 + rin;
                int chunk = k16 * 2 + (mat & 1);
                uint32_t so = swz_off(nrow, chunk);
                uint32_t b0, b1, b2, b3;
                ldsm_x4(b0, b1, b2, b3, st + BW_OFF + so);
                uint32_t bf[2][2] = { {b0, b1}, {b2, b3} };
                #pragma unroll
                for (int mt = 0; mt < 2; mt++) {
                    #pragma unroll
                    for (int j = 0; j < 2; j++) {
                        float* d = acc[mt][nt * 2 + j];
                        mma_f16(d, ah[mt], bf[j]);
                        mma_f16(d, al[mt], bf[j]);
                    }
                }
            }
        }
        __syncthreads();
    }

    // Epilogue: single fp16 head-split store (Q pre-scaled by 1/8)
    const float scale = (which == 0) ? 0.125f : 1.0f;
    #pragma unroll
    for (int mt = 0; mt < 2; mt++) {
        int row0 = m0 + wm * 32 + mt * 16 + (lane >> 2);
        #pragma unroll
        for (int nf = 0; nf < 8; nf++) {
            int col = n0 + wn * 64 + nf * 8 + 2 * (lane & 3);
            int h0 = col >> 6, d0 = col & 63;
            #pragma unroll
            for (int half = 0; half < 2; half++) {
                int m = row0 + half * 8;
                int b = m >> 11, t = m & 2047;
                __half2 hv = __floats2half2_rn(acc[mt][nf][half*2]   * scale,
                                               acc[mt][nf][half*2+1] * scale);
                size_t off = ((size_t)(b * NH + h0) * T + t) * DH + d0;
                *(__half2*)(Og + off) = hv;
            }
        }
    }
}

// ---------------------------------------------------------------------------
// Kernel 2: flash attention, fp16 single-term S and PV.
// grid = (QT128=16, BH=64), 256 threads (8 warps x 16 q-rows).
// ---------------------------------------------------------------------------
#define AT_K 0
#define AT_V 8192
#define AT_STAGE 16384
#define ATT_SMEM (2 * AT_STAGE + 1024)

__global__ __launch_bounds__(256) void attn_mma_kernel()
{
    extern __shared__ char dsm[];
    __shared__ float red[8][64];
    char* smp = (char*)(((uintptr_t)dsm + 1023) & ~(uintptr_t)1023);
    const uint32_t sb = smem_u32(smp);

    const int qt = blockIdx.x;
    const int bh = blockIdx.y;
    const int tid = threadIdx.x;
    const int wid = tid >> 5;
    const int lane = tid & 31;
    const int q0 = qt * 128;

    const char* __restrict__ QP = (const char*)(QhG + (size_t)bh * T * DH);
    const char* __restrict__ KP = (const char*)(KhG + (size_t)bh * T * DH);
    const char* __restrict__ VP = (const char*)(VhG + (size_t)bh * T * DH);

    // ---- load Q tile (128 x 64 fp16) into stage0, extract A-frags ----
    #pragma unroll
    for (int it = 0; it < 4; it++) {
        int idx = tid + 256 * it;
        int r = idx >> 3, c = idx & 7;
        cp16(sb + swz_off(r, c), QP + (size_t)(q0 + r) * 128 + c * 16);
    }
    CP_COMMIT();
    CP_WAIT0();
    __syncthreads();

    uint32_t qh[4][4];
    #pragma unroll
    for (int k16 = 0; k16 < 4; k16++) {
        int row = wid * 16 + (lane & 15);
        int chunk = k16 * 2 + (lane >> 4);
        uint32_t so = swz_off(row, chunk);
        ldsm_x4(qh[k16][0], qh[k16][1], qh[k16][2], qh[k16][3], sb + so);
    }
    __syncthreads();

    // ---- KV pipeline (K,V single fp16: 8KB each per 64-key tile) ----
    auto issue_kv = [&](int i) {
        const int s0 = i * 64;
        const uint32_t st = sb + (i & 1) * AT_STAGE;
        #pragma unroll
        for (int it = 0; it < 2; it++) {
            int idx = tid + 256 * it;
            int r = idx >> 3, c = idx & 7;
            uint32_t so = swz_off(r, c);
            size_t g = (size_t)(s0 + r) * 128 + c * 16;
            cp16(st + AT_K + so, KP + g);
            cp16(st + AT_V + so, VP + g);
        }
        CP_COMMIT();
    };

    issue_kv(0);
    issue_kv(1);

    float m0 = -1e30f, m1 = -1e30f, l0 = 0.f, l1 = 0.f;
    float oacc[8][4];
    #pragma unroll
    for (int t = 0; t < 8; t++)
        #pragma unroll
        for (int q = 0; q < 4; q++) oacc[t][q] = 0.f;

    for (int i = 0; i < 32; i++) {
        if (i < 31) { CP_WAIT1(); } else { CP_WAIT0(); }
        __syncthreads();

        const uint32_t st = sb + (i & 1) * AT_STAGE;

        // ---- S = Q K^T (single term) ----
        float sacc[8][4];
        #pragma unroll
        for (int t = 0; t < 8; t++)
            #pragma unroll
            for (int q = 0; q < 4; q++) sacc[t][q] = 0.f;

        #pragma unroll
        for (int k16 = 0; k16 < 4; k16++) {
            #pragma unroll
            for (int nt = 0; nt < 4; nt++) {
                int mat = lane >> 3, rin = lane & 7;
                int nrow = nt * 16 + (mat >> 1) * 8 + rin;
                int chunk = k16 * 2 + (mat & 1);
                uint32_t so = swz_off(nrow, chunk);
                uint32_t b0, b1, b2, b3;
                ldsm_x4(b0, b1, b2, b3, st + AT_K + so);
                uint32_t bf01[2] = {b0, b1}, bf23[2] = {b2, b3};
                mma_f16(sacc[2*nt],   qh[k16], bf01);
                mma_f16(sacc[2*nt+1], qh[k16], bf23);
            }
        }

        // ---- online softmax (rows: r0 = lane>>2, r1 = r0+8) ----
        float ml0 = -1e30f, ml1 = -1e30f;
        #pragma unroll
        for (int t = 0; t < 8; t++) {
            ml0 = fmaxf(ml0, fmaxf(sacc[t][0], sacc[t][1]));
            ml1 = fmaxf(ml1, fmaxf(sacc[t][2], sacc[t][3]));
        }
        ml0 = fmaxf(ml0, __shfl_xor_sync(0xffffffffu, ml0, 1));
        ml0 = fmaxf(ml0, __shfl_xor_sync(0xffffffffu, ml0, 2));
        ml1 = fmaxf(ml1, __shfl_xor_sync(0xffffffffu, ml1, 1));
        ml1 = fmaxf(ml1, __shfl_xor_sync(0xffffffffu, ml1, 2));
        float mn0 = fmaxf(m0, ml0), mn1 = fmaxf(m1, ml1);

        float rs0 = 0.f, rs1 = 0.f;
        uint32_t phA[8], phB[8];
        #pragma unroll
        for (int t = 0; t < 8; t++) {
            float p0 = __expf(sacc[t][0] - mn0);
            float p1 = __expf(sacc[t][1] - mn0);
            float p2 = __expf(sacc[t][2] - mn1);
            float p3 = __expf(sacc[t][3] - mn1);
            rs0 += p0 + p1;
            rs1 += p2 + p3;
            __half2 hA = __floats2half2_rn(p0, p1);
            __half2 hB = __floats2half2_rn(p2, p3);
            phA[t] = *(uint32_t*)&hA;
            phB[t] = *(uint32_t*)&hB;
        }
        rs0 += __shfl_xor_sync(0xffffffffu, rs0, 1);
        rs0 += __shfl_xor_sync(0xffffffffu, rs0, 2);
        rs1 += __shfl_xor_sync(0xffffffffu, rs1, 1);
        rs1 += __shfl_xor_sync(0xffffffffu, rs1, 2);

        float a0 = __expf(m0 - mn0), a1 = __expf(m1 - mn1);
        l0 = l0 * a0 + rs0;
        l1 = l1 * a1 + rs1;
        m0 = mn0; m1 = mn1;
        #pragma unroll
        for (int t = 0; t < 8; t++) {
            oacc[t][0] *= a0; oacc[t][1] *= a0;
            oacc[t][2] *= a1; oacc[t][3] *= a1;
        }

        // ---- O += P V (single term), V via ldmatrix.trans ----
        #pragma unroll
        for (int j = 0; j < 4; j++) {
            uint32_t Ah[4] = { phA[2*j], phB[2*j], phA[2*j+1], phB[2*j+1] };
            #pragma unroll
            for (int tt = 0; tt < 8; tt += 2) {
                int mi = lane >> 3;
                int row = 16*j + (mi & 1) * 8 + (lane & 7);
                int chunk = tt + (mi >> 1);
                uint32_t so = swz_off(row, chunk);
                uint32_t b0, b1, b2, b3;
                ldsm_x4_t(b0, b1, b2, b3, st + AT_V + so);
                uint32_t bf01[2] = {b0, b1}, bf23[2] = {b2, b3};
                mma_f16(oacc[tt],   Ah, bf01);
                mma_f16(oacc[tt+1], Ah, bf23);
            }
        }
        __syncthreads();
        if (i + 2 < 32) issue_kv(i + 2);
    }

    // ---- column sums of O/l over this warp's 16 rows ----
    float inv0 = 1.f / l0, inv1 = 1.f / l1;
    float cp0[8], cp1[8];
    #pragma unroll
    for (int t = 0; t < 8; t++) {
        cp0[t] = oacc[t][0] * inv0 + oacc[t][2] * inv1;
        cp1[t] = oacc[t][1] * inv0 + oacc[t][3] * inv1;
    }
    #pragma unroll
    for (int msk = 4; msk < 32; msk <<= 1) {
        #pragma unroll
        for (int t = 0; t < 8; t++) {
            cp0[t] += __shfl_xor_sync(0xffffffffu, cp0[t], msk);
            cp1[t] += __shfl_xor_sync(0xffffffffu, cp1[t], msk);
        }
    }
    if ((lane >> 2) == 0) {
        #pragma unroll
        for (int t = 0; t < 8; t++) {
            red[wid][8*t + 2*lane + 0] = cp0[t];
            red[wid][8*t + 2*lane + 1] = cp1[t];
        }
    }
    __syncthreads();
    if (tid < 64) {
        float s = 0.f;
        #pragma unroll
        for (int w = 0; w < 8; w++) s += red[w][tid];
        Psum[((size_t)bh * QT128 + qt) * DH + tid] = s;
    }
}

// ---------------------------------------------------------------------------
// Kernel 3 & 4
// ---------------------------------------------------------------------------
__global__ __launch_bounds__(256) void reduce_kernel()
{
    int idx = blockIdx.x * 256 + threadIdx.x;
    int b = idx >> 10;
    int h = (idx >> 6) & 15;
    int d = idx & 63;
    int bh = b * NH + h;
    float s = 0.f;
    #pragma unroll
    for (int qt = 0; qt < QT128; qt++)
        s += Psum[((size_t)bh * QT128 + qt) * DH + d];
    Mctx[idx] = s * (1.0f / T);
}

__global__ __launch_bounds__(256) void out_kernel(
    const float* __restrict__ Wo, const float* __restrict__ bo,
    float* __restrict__ out)
{
    int gw = (blockIdx.x * 256 + threadIdx.x) >> 5;
    int lane = threadIdx.x & 31;
    int b = gw >> 10;
    int n = gw & 1023;
    const float* __restrict__ wrow = Wo + (size_t)n * H;
    const float* __restrict__ mrow = Mctx + b * H;
    float s = 0.f;
    #pragma unroll 4
    for (int k = lane; k < H; k += 32) s += mrow[k] * wrow[k];
    #pragma unroll
    for (int d = 16; d; d >>= 1) s += __shfl_xor_sync(0xffffffffu, s, d);
    if (lane == 0) out[b * H + n] = s + bo[n];
}

// ---------------------------------------------------------------------------
extern "C" void kernel_launch(void* const* d_in, const int* in_sizes, int n_in,
                              void* d_out, int out_size)
{
    const float* x  = (const float*)d_in[0];
    const float* Wq = (const float*)d_in[1];
    const float* Wk = (const float*)d_in[2];
    const float* Wv = (const float*)d_in[3];
    const float* Wo = (const float*)d_in[4];
    const float* bo = (const float*)d_in[5];
    float* out = (float*)d_out;

    cudaFuncSetAttribute(proj_mma_kernel,
                         cudaFuncAttributeMaxDynamicSharedMemorySize, PROJ_SMEM);
    cudaFuncSetAttribute(attn_mma_kernel,
                         cudaFuncAttributeMaxDynamicSharedMemorySize, ATT_SMEM);

    convert_x_kernel<<<(B*T*H)/(256*4), 256>>>(x);
    convert_w_kernel<<<dim3((H*H)/(256*4), 3), 256>>>(Wq, Wk, Wv);
    proj_mma_kernel<<<dim3(64, 8, 3), 256, PROJ_SMEM>>>();
    attn_mma_kernel<<<dim3(QT128, BH), 256, ATT_SMEM>>>();
    reduce_kernel<<<16, 256>>>();
    out_kernel<<<512, 256>>>(Wo, bo, out);
}

// round 8
// speedup vs baseline: 9.4838x; 1.2643x over previous
#include <cuda_runtime.h>
#include <cuda_fp16.h>
#include <cstdint>

#define B 4
#define T 2048
#define H 1024
#define NH 16
#define DH 64
#define BH (B*NH)
#define QT128 (T/128)     // 16 q-tiles of 128

// ---------------- mma.sync helpers (baseline ISA) ----------------
__device__ __forceinline__ uint32_t smem_u32(const void* p) {
    uint32_t a;
    asm("{ .reg .u64 t; cvta.to.shared.u64 t, %1; cvt.u32.u64 %0, t; }" : "=r"(a) : "l"(p));
    return a;
}
__device__ __forceinline__ void ldsm_x4(uint32_t& r0, uint32_t& r1, uint32_t& r2,
                                        uint32_t& r3, uint32_t addr) {
    asm volatile("ldmatrix.sync.aligned.m8n8.x4.shared.b16 {%0,%1,%2,%3}, [%4];"
                 : "=r"(r0), "=r"(r1), "=r"(r2), "=r"(r3) : "r"(addr));
}
__device__ __forceinline__ void ldsm_x4_t(uint32_t& r0, uint32_t& r1, uint32_t& r2,
                                          uint32_t& r3, uint32_t addr) {
    asm volatile("ldmatrix.sync.aligned.m8n8.x4.trans.shared.b16 {%0,%1,%2,%3}, [%4];"
                 : "=r"(r0), "=r"(r1), "=r"(r2), "=r"(r3) : "r"(addr));
}
__device__ __forceinline__ void mma_f16(float* d, const uint32_t* a, const uint32_t* b) {
    asm volatile("mma.sync.aligned.m16n8k16.row.col.f32.f16.f16.f32 "
        "{%0,%1,%2,%3}, {%4,%5,%6,%7}, {%8,%9}, {%0,%1,%2,%3};"
        : "+f"(d[0]), "+f"(d[1]), "+f"(d[2]), "+f"(d[3])
        : "r"(a[0]), "r"(a[1]), "r"(a[2]), "r"(a[3]), "r"(b[0]), "r"(b[1]));
}
__device__ __forceinline__ void cp16(uint32_t saddr, const void* g) {
    asm volatile("cp.async.cg.shared.global [%0], [%1], 16;" :: "r"(saddr), "l"(g));
}
#define CP_COMMIT() asm volatile("cp.async.commit_group;" ::: "memory")
#define CP_WAIT0()  asm volatile("cp.async.wait_group 0;" ::: "memory")
#define CP_WAIT1()  asm volatile("cp.async.wait_group 1;" ::: "memory")

// swizzled byte offset of 16B chunk c (0..7) in row r of a 128B-row tile
__device__ __forceinline__ uint32_t swz_off(int r, int c) {
    return (uint32_t)(r * 128 + ((c ^ (r & 7)) << 4));
}

// ---------------- scratch ----------------
__device__ float Psum[BH * QT128 * DH];
__device__ float Mctx[B * H];
__device__ __half Xh[(size_t)B * T * H];      // x fp16
__device__ __half Whg[3 * H * H];             // W fp16
__device__ __half QhG[(size_t)BH * T * DH];   // Q fp16, pre-scaled by 0.125*log2(e)
__device__ __half KhG[(size_t)BH * T * DH];   // K fp16
__device__ __half VhG[(size_t)BH * T * DH];   // V fp16

// ---------------------------------------------------------------------------
// Convert kernels
// ---------------------------------------------------------------------------
__global__ __launch_bounds__(256) void convert_x_kernel(const float* __restrict__ x)
{
    int i = blockIdx.x * 256 + threadIdx.x;
    float4 v = ((const float4*)x)[i];
    __half hs[4] = { __float2half_rn(v.x), __float2half_rn(v.y),
                     __float2half_rn(v.z), __float2half_rn(v.w) };
    *(uint2*)(Xh + (size_t)i*4) = *(uint2*)hs;
}

__global__ __launch_bounds__(256) void convert_w_kernel(
    const float* __restrict__ Wq, const float* __restrict__ Wk,
    const float* __restrict__ Wv)
{
    const float* w = (blockIdx.y == 0) ? Wq : (blockIdx.y == 1) ? Wk : Wv;
    int i = blockIdx.x * 256 + threadIdx.x;
    float4 v = ((const float4*)w)[i];
    __half hs[4] = { __float2half_rn(v.x), __float2half_rn(v.y),
                     __float2half_rn(v.z), __float2half_rn(v.w) };
    *(uint2*)(Whg + (size_t)blockIdx.y * H * H + (size_t)i*4) = *(uint2*)hs;
}

// ---------------------------------------------------------------------------
// Kernel 1: projection GEMM (mma.sync fp16, single-term).
// Block 128x128, K-stage 64, 8 warps (4m x 2n). grid = (64, 8, 3).
// ---------------------------------------------------------------------------
#define BKP 64
#define NSTG (H / BKP)
#define TILE_B (128 * 128)        // 16KB tile (128 rows x 64 fp16)
#define AH_OFF 0
#define BW_OFF (TILE_B)
#define STAGE_B (2 * TILE_B)      // 32KB
#define PROJ_SMEM (2 * STAGE_B + 1024)

__global__ __launch_bounds__(256) void proj_mma_kernel()
{
    extern __shared__ char dsm[];
    char* smp = (char*)(((uintptr_t)dsm + 1023) & ~(uintptr_t)1023);
    const uint32_t sb = smem_u32(smp);

    const int which = blockIdx.z;
    const int m0 = blockIdx.x * 128;
    const int n0 = blockIdx.y * 128;
    const int tid = threadIdx.x;
    const int wid = tid >> 5;
    const int lane = tid & 31;
    const int wm = wid & 3;
    const int wn = wid >> 2;

    const char* __restrict__ XhB = (const char*)Xh;
    const char* __restrict__ WB  = (const char*)(Whg + (size_t)which * H * H);
    __half* __restrict__ Og = (which == 0) ? QhG : (which == 1) ? KhG : VhG;

    float acc[2][8][4];
    #pragma unroll
    for (int i = 0; i < 2; i++)
        #pragma unroll
        for (int j = 0; j < 8; j++)
            #pragma unroll
            for (int q = 0; q < 4; q++) acc[i][j][q] = 0.f;

    auto issue_stage = [&](int i) {
        const int k0 = i * BKP;
        const uint32_t st = sb + (i & 1) * STAGE_B;
        #pragma unroll
        for (int it = 0; it < 4; it++) {
            int idx = tid + 256 * it;
            int r = idx >> 3, c = idx & 7;
            uint32_t so = swz_off(r, c);
            size_t ga = ((size_t)(m0 + r) * H + k0) * 2 + c * 16;
            size_t gb = ((size_t)(n0 + r) * H + k0) * 2 + c * 16;
            cp16(st + AH_OFF + so, XhB + ga);
            cp16(st + BW_OFF + so, WB + gb);
        }
        CP_COMMIT();
    };

    issue_stage(0);

    for (int i = 0; i < NSTG; i++) {
        CP_WAIT0();
        __syncthreads();
        if (i + 1 < NSTG) issue_stage(i + 1);

        const uint32_t st = sb + (i & 1) * STAGE_B;

        #pragma unroll
        for (int k16 = 0; k16 < 4; k16++) {
            uint32_t ah[2][4];
            #pragma unroll
            for (int mt = 0; mt < 2; mt++) {
                int row = wm * 32 + mt * 16 + (lane & 15);
                int chunk = k16 * 2 + (lane >> 4);
                uint32_t so = swz_off(row, chunk);
                ldsm_x4(ah[mt][0], ah[mt][1], ah[mt][2], ah[mt][3], st + AH_OFF + so);
            }
            #pragma unroll
            for (int nt = 0; nt < 4; nt++) {
                int mat = lane >> 3, rin = lane & 7;
                int nrow = wn * 64 + nt * 16 + (mat >> 1) * 8 + rin;
                int chunk = k16 * 2 + (mat & 1);
                uint32_t so = swz_off(nrow, chunk);
                uint32_t b0, b1, b2, b3;
                ldsm_x4(b0, b1, b2, b3, st + BW_OFF + so);
                uint32_t bf[2][2] = { {b0, b1}, {b2, b3} };
                #pragma unroll
                for (int mt = 0; mt < 2; mt++) {
                    #pragma unroll
                    for (int j = 0; j < 2; j++)
                        mma_f16(acc[mt][nt * 2 + j], ah[mt], bf[j]);
                }
            }
        }
        __syncthreads();
    }

    // Epilogue: fp16 head-split store. Q pre-scaled by 0.125*log2(e).
    const float scale = (which == 0) ? 0.18033688011112042f : 1.0f;
    #pragma unroll
    for (int mt = 0; mt < 2; mt++) {
        int row0 = m0 + wm * 32 + mt * 16 + (lane >> 2);
        #pragma unroll
        for (int nf = 0; nf < 8; nf++) {
            int col = n0 + wn * 64 + nf * 8 + 2 * (lane & 3);
            int h0 = col >> 6, d0 = col & 63;
            #pragma unroll
            for (int half = 0; half < 2; half++) {
                int m = row0 + half * 8;
                int b = m >> 11, t = m & 2047;
                __half2 hv = __floats2half2_rn(acc[mt][nf][half*2]   * scale,
                                               acc[mt][nf][half*2+1] * scale);
                size_t off = ((size_t)(b * NH + h0) * T + t) * DH + d0;
                *(__half2*)(Og + off) = hv;
            }
        }
    }
}

// ---------------------------------------------------------------------------
// Kernel 2: flash attention, fp16, exp2-domain softmax.
// grid = (QT128=16, BH=64), 256 threads (8 warps x 16 q-rows).
// ---------------------------------------------------------------------------
#define AT_K 0
#define AT_V 8192
#define AT_STAGE 16384
#define ATT_SMEM (2 * AT_STAGE + 1024)

__global__ __launch_bounds__(256) void attn_mma_kernel()
{
    extern __shared__ char dsm[];
    __shared__ float red[8][64];
    char* smp = (char*)(((uintptr_t)dsm + 1023) & ~(uintptr_t)1023);
    const uint32_t sb = smem_u32(smp);

    const int qt = blockIdx.x;
    const int bh = blockIdx.y;
    const int tid = threadIdx.x;
    const int wid = tid >> 5;
    const int lane = tid & 31;
    const int q0 = qt * 128;

    const char* __restrict__ QP = (const char*)(QhG + (size_t)bh * T * DH);
    const char* __restrict__ KP = (const char*)(KhG + (size_t)bh * T * DH);
    const char* __restrict__ VP = (const char*)(VhG + (size_t)bh * T * DH);

    // ---- load Q tile (128 x 64 fp16) into stage0, extract A-frags ----
    #pragma unroll
    for (int it = 0; it < 4; it++) {
        int idx = tid + 256 * it;
        int r = idx >> 3, c = idx & 7;
        cp16(sb + swz_off(r, c), QP + (size_t)(q0 + r) * 128 + c * 16);
    }
    CP_COMMIT();
    CP_WAIT0();
    __syncthreads();

    uint32_t qh[4][4];
    #pragma unroll
    for (int k16 = 0; k16 < 4; k16++) {
        int row = wid * 16 + (lane & 15);
        int chunk = k16 * 2 + (lane >> 4);
        uint32_t so = swz_off(row, chunk);
        ldsm_x4(qh[k16][0], qh[k16][1], qh[k16][2], qh[k16][3], sb + so);
    }
    __syncthreads();

    // ---- KV pipeline ----
    auto issue_kv = [&](int i) {
        const int s0 = i * 64;
        const uint32_t st = sb + (i & 1) * AT_STAGE;
        #pragma unroll
        for (int it = 0; it < 2; it++) {
            int idx = tid + 256 * it;
            int r = idx >> 3, c = idx & 7;
            uint32_t so = swz_off(r, c);
            size_t g = (size_t)(s0 + r) * 128 + c * 16;
            cp16(st + AT_K + so, KP + g);
            cp16(st + AT_V + so, VP + g);
        }
        CP_COMMIT();
    };

    issue_kv(0);
    issue_kv(1);

    float m0 = -1e30f, m1 = -1e30f, l0 = 0.f, l1 = 0.f;
    float oacc[8][4];
    #pragma unroll
    for (int t = 0; t < 8; t++)
        #pragma unroll
        for (int q = 0; q < 4; q++) oacc[t][q] = 0.f;

    for (int i = 0; i < 32; i++) {
        if (i < 31) { CP_WAIT1(); } else { CP_WAIT0(); }
        __syncthreads();

        const uint32_t st = sb + (i & 1) * AT_STAGE;

        // ---- S = Q K^T (log2 domain: Q pre-scaled) ----
        float sacc[8][4];
        #pragma unroll
        for (int t = 0; t < 8; t++)
            #pragma unroll
            for (int q = 0; q < 4; q++) sacc[t][q] = 0.f;

        #pragma unroll
        for (int k16 = 0; k16 < 4; k16++) {
            #pragma unroll
            for (int nt = 0; nt < 4; nt++) {
                int mat = lane >> 3, rin = lane & 7;
                int nrow = nt * 16 + (mat >> 1) * 8 + rin;
                int chunk = k16 * 2 + (mat & 1);
                uint32_t so = swz_off(nrow, chunk);
                uint32_t b0, b1, b2, b3;
                ldsm_x4(b0, b1, b2, b3, st + AT_K + so);
                uint32_t bf01[2] = {b0, b1}, bf23[2] = {b2, b3};
                mma_f16(sacc[2*nt],   qh[k16], bf01);
                mma_f16(sacc[2*nt+1], qh[k16], bf23);
            }
        }

        // ---- online softmax (exp2 domain) ----
        float ml0 = -1e30f, ml1 = -1e30f;
        #pragma unroll
        for (int t = 0; t < 8; t++) {
            ml0 = fmaxf(ml0, fmaxf(sacc[t][0], sacc[t][1]));
            ml1 = fmaxf(ml1, fmaxf(sacc[t][2], sacc[t][3]));
        }
        ml0 = fmaxf(ml0, __shfl_xor_sync(0xffffffffu, ml0, 1));
        ml0 = fmaxf(ml0, __shfl_xor_sync(0xffffffffu, ml0, 2));
        ml1 = fmaxf(ml1, __shfl_xor_sync(0xffffffffu, ml1, 1));
        ml1 = fmaxf(ml1, __shfl_xor_sync(0xffffffffu, ml1, 2));
        float mn0 = fmaxf(m0, ml0), mn1 = fmaxf(m1, ml1);

        float rs0 = 0.f, rs1 = 0.f;
        uint32_t phA[8], phB[8];
        #pragma unroll
        for (int t = 0; t < 8; t++) {
            float p0 = exp2f(sacc[t][0] - mn0);
            float p1 = exp2f(sacc[t][1] - mn0);
            float p2 = exp2f(sacc[t][2] - mn1);
            float p3 = exp2f(sacc[t][3] - mn1);
            rs0 += p0 + p1;
            rs1 += p2 + p3;
            __half2 hA = __floats2half2_rn(p0, p1);
            __half2 hB = __floats2half2_rn(p2, p3);
            phA[t] = *(uint32_t*)&hA;
            phB[t] = *(uint32_t*)&hB;
        }
        rs0 += __shfl_xor_sync(0xffffffffu, rs0, 1);
        rs0 += __shfl_xor_sync(0xffffffffu, rs0, 2);
        rs1 += __shfl_xor_sync(0xffffffffu, rs1, 1);
        rs1 += __shfl_xor_sync(0xffffffffu, rs1, 2);

        float a0 = exp2f(m0 - mn0), a1 = exp2f(m1 - mn1);
        l0 = l0 * a0 + rs0;
        l1 = l1 * a1 + rs1;
        m0 = mn0; m1 = mn1;
        #pragma unroll
        for (int t = 0; t < 8; t++) {
            oacc[t][0] *= a0; oacc[t][1] *= a0;
            oacc[t][2] *= a1; oacc[t][3] *= a1;
        }

        // ---- O += P V, V via ldmatrix.trans ----
        #pragma unroll
        for (int j = 0; j < 4; j++) {
            uint32_t Ah[4] = { phA[2*j], phB[2*j], phA[2*j+1], phB[2*j+1] };
            #pragma unroll
            for (int tt = 0; tt < 8; tt += 2) {
                int mi = lane >> 3;
                int row = 16*j + (mi & 1) * 8 + (lane & 7);
                int chunk = tt + (mi >> 1);
                uint32_t so = swz_off(row, chunk);
                uint32_t b0, b1, b2, b3;
                ldsm_x4_t(b0, b1, b2, b3, st + AT_V + so);
                uint32_t bf01[2] = {b0, b1}, bf23[2] = {b2, b3};
                mma_f16(oacc[tt],   Ah, bf01);
                mma_f16(oacc[tt+1], Ah, bf23);
            }
        }
        __syncthreads();
        if (i + 2 < 32) issue_kv(i + 2);
    }

    // ---- column sums of O/l over this warp's 16 rows ----
    float inv0 = 1.f / l0, inv1 = 1.f / l1;
    float cp0[8], cp1[8];
    #pragma unroll
    for (int t = 0; t < 8; t++) {
        cp0[t] = oacc[t][0] * inv0 + oacc[t][2] * inv1;
        cp1[t] = oacc[t][1] * inv0 + oacc[t][3] * inv1;
    }
    #pragma unroll
    for (int msk = 4; msk < 32; msk <<= 1) {
        #pragma unroll
        for (int t = 0; t < 8; t++) {
            cp0[t] += __shfl_xor_sync(0xffffffffu, cp0[t], msk);
            cp1[t] += __shfl_xor_sync(0xffffffffu, cp1[t], msk);
        }
    }
    if ((lane >> 2) == 0) {
        #pragma unroll
        for (int t = 0; t < 8; t++) {
            red[wid][8*t + 2*lane + 0] = cp0[t];
            red[wid][8*t + 2*lane + 1] = cp1[t];
        }
    }
    __syncthreads();
    if (tid < 64) {
        float s = 0.f;
        #pragma unroll
        for (int w = 0; w < 8; w++) s += red[w][tid];
        Psum[((size_t)bh * QT128 + qt) * DH + tid] = s;
    }
}

// ---------------------------------------------------------------------------
// Kernel 3 & 4
// ---------------------------------------------------------------------------
__global__ __launch_bounds__(256) void reduce_kernel()
{
    int idx = blockIdx.x * 256 + threadIdx.x;
    int b = idx >> 10;
    int h = (idx >> 6) & 15;
    int d = idx & 63;
    int bh = b * NH + h;
    float s = 0.f;
    #pragma unroll
    for (int qt = 0; qt < QT128; qt++)
        s += Psum[((size_t)bh * QT128 + qt) * DH + d];
    Mctx[idx] = s * (1.0f / T);
}

__global__ __launch_bounds__(256) void out_kernel(
    const float* __restrict__ Wo, const float* __restrict__ bo,
    float* __restrict__ out)
{
    int gw = (blockIdx.x * 256 + threadIdx.x) >> 5;
    int lane = threadIdx.x & 31;
    int b = gw >> 10;
    int n = gw & 1023;
    const float* __restrict__ wrow = Wo + (size_t)n * H;
    const float* __restrict__ mrow = Mctx + b * H;
    float s = 0.f;
    #pragma unroll 4
    for (int k = lane; k < H; k += 32) s += mrow[k] * wrow[k];
    #pragma unroll
    for (int d = 16; d; d >>= 1) s += __shfl_xor_sync(0xffffffffu, s, d);
    if (lane == 0) out[b * H + n] = s + bo[n];
}

// ---------------------------------------------------------------------------
extern "C" void kernel_launch(void* const* d_in, const int* in_sizes, int n_in,
                              void* d_out, int out_size)
{
    const float* x  = (const float*)d_in[0];
    const float* Wq = (const float*)d_in[1];
    const float* Wk = (const float*)d_in[2];
    const float* Wv = (const float*)d_in[3];
    const float* Wo = (const float*)d_in[4];
    const float* bo = (const float*)d_in[5];
    float* out = (float*)d_out;

    cudaFuncSetAttribute(proj_mma_kernel,
                         cudaFuncAttributeMaxDynamicSharedMemorySize, PROJ_SMEM);
    cudaFuncSetAttribute(attn_mma_kernel,
                         cudaFuncAttributeMaxDynamicSharedMemorySize, ATT_SMEM);

    convert_x_kernel<<<(B*T*H)/(256*4), 256>>>(x);
    convert_w_kernel<<<dim3((H*H)/(256*4), 3), 256>>>(Wq, Wk, Wv);
    proj_mma_kernel<<<dim3(64, 8, 3), 256, PROJ_SMEM>>>();
    attn_mma_kernel<<<dim3(QT128, BH), 256, ATT_SMEM>>>();
    reduce_kernel<<<16, 256>>>();
    out_kernel<<<512, 256>>>(Wo, bo, out);
}